// round 10
// baseline (speedup 1.0000x reference)
#include <cuda_runtime.h>
#include <cuda_fp16.h>

#define TT 512
#define SDIM 8
#define ODIM 4
#define NTHREADS 512
#define NCTA 128
#define ROWS 8
#define ROWF 80   // 4 kh-segments of 16 floats, 4-float skew between segments

typedef unsigned long long ull;

// fp16 weights as uint2 quads: arr[q][j] = {half2(4q,4q+1), half2(4q+2,4q+3)}
struct __align__(16) Smem {
    uint2 Wff[3][16][64];   // W_from_W, W_from_I, W_from_A
    uint2 Wg[2][16][64];    // W_gate rows [I | A]
    uint2 Iz[3][16][64];
    uint2 Ir[3][16][64];
    uint2 Ih[3][16][64];    // rows [Wn | r*I | A]
    uint2 Aff[3][16][64];
    uint2 Agt[2][16][64];   // rows [Wn | In]
    float sW[2][ROWS][ROWF];  // double-buffered states, skewed rows
    float sI[2][ROWS][ROWF];
    float sA[2][ROWS][ROWF];
    float sRI[ROWS][ROWF];
    float xs[ROWS][SDIM];
};

extern __shared__ char smem_raw[];

__device__ __forceinline__ float tanh_f(float x) {
    x = fminf(fmaxf(x, -9.0f), 9.0f);
    float e = __expf(2.0f * x);
    return __fdividef(e - 1.0f, e + 1.0f);
}
__device__ __forceinline__ float sigm_f(float x) {
    return __fdividef(1.0f, 1.0f + __expf(-x));
}

__device__ __forceinline__ ull h2f2(unsigned int h) {
    ull r;
    asm("{\n\t"
        ".reg .b16 l16, h16;\n\t"
        ".reg .f32 fl, fh;\n\t"
        "mov.b32 {l16, h16}, %1;\n\t"
        "cvt.f32.f16 fl, l16;\n\t"
        "cvt.f32.f16 fh, h16;\n\t"
        "mov.b64 %0, {fl, fh};\n\t"
        "}" : "=l"(r) : "r"(h));
    return r;
}
__device__ __forceinline__ void fma2(ull& d, ull a, ull b) {
    asm("fma.rn.f32x2 %0, %1, %2, %0;" : "+l"(d) : "l"(a), "l"(b));
}
__device__ __forceinline__ float hsum2(ull a, ull b) {
    float ax, ay, bx, by;
    asm("mov.b64 {%0, %1}, %2;" : "=f"(ax), "=f"(ay) : "l"(a));
    asm("mov.b64 {%0, %1}, %2;" : "=f"(bx), "=f"(by) : "l"(b));
    return (ax + bx) + (ay + by);
}
// 16-k partial -> full 64-k dot: reduce across kh (lane bits 3,4)
__device__ __forceinline__ float red16(ull P, ull Q) {
    float p = hsum2(P, Q);
    p += __shfl_xor_sync(0xffffffffu, p, 8);
    p += __shfl_xor_sync(0xffffffffu, p, 16);
    return p;
}
// group barrier: 256 threads of row-half group (barrier id 1 or 2)
__device__ __forceinline__ void gbar(int id) {
    asm volatile("bar.sync %0, 256;" :: "r"(id) : "memory");
}

__device__ __forceinline__ void stage4(uint2 (&dst)[16][64],
                                       const float* __restrict__ src) {
#pragma unroll 1
    for (int i = threadIdx.x; i < 1024; i += NTHREADS) {
        int q = i >> 6, jj = i & 63;
        __half2 a = __floats2half2_rn(src[(4 * q + 0) * 64 + jj],
                                      src[(4 * q + 1) * 64 + jj]);
        __half2 b = __floats2half2_rn(src[(4 * q + 2) * 64 + jj],
                                      src[(4 * q + 3) * 64 + jj]);
        uint2 v;
        v.x = *reinterpret_cast<unsigned int*>(&a);
        v.y = *reinterpret_cast<unsigned int*>(&b);
        dst[q][jj] = v;
    }
}

__global__ void __launch_bounds__(NTHREADS, 1)
anima_kernel(const float* __restrict__ x,
             const float* __restrict__ we_w, const float* __restrict__ we_b,
             const float* __restrict__ WfW, const float* __restrict__ WfI,
             const float* __restrict__ WfA,
             const float* __restrict__ Wg_w, const float* __restrict__ Wg_b,
             const float* __restrict__ Iz_w, const float* __restrict__ Iz_b,
             const float* __restrict__ Ir_w, const float* __restrict__ Ir_b,
             const float* __restrict__ Ih_w, const float* __restrict__ Ih_b,
             const float* __restrict__ AfW, const float* __restrict__ AfI,
             const float* __restrict__ AfA,
             const float* __restrict__ Ag_w, const float* __restrict__ Ag_b,
             const float* __restrict__ phi_w, const float* __restrict__ phi_b,
             float* __restrict__ out) {
    Smem* S = reinterpret_cast<Smem*>(smem_raw);
    const int tid = threadIdx.x;

    // ---- one-time staging
    stage4(S->Wff[0], WfW);
    stage4(S->Wff[1], WfI);
    stage4(S->Wff[2], WfA);
    stage4(S->Wg[0], Wg_w);
    stage4(S->Wg[1], Wg_w + 64 * 64);
    stage4(S->Iz[0], Iz_w);
    stage4(S->Iz[1], Iz_w + 64 * 64);
    stage4(S->Iz[2], Iz_w + 128 * 64);
    stage4(S->Ir[0], Ir_w);
    stage4(S->Ir[1], Ir_w + 64 * 64);
    stage4(S->Ir[2], Ir_w + 128 * 64);
    stage4(S->Ih[0], Ih_w);
    stage4(S->Ih[1], Ih_w + 64 * 64);
    stage4(S->Ih[2], Ih_w + 128 * 64);
    stage4(S->Aff[0], AfW);
    stage4(S->Aff[1], AfI);
    stage4(S->Aff[2], AfA);
    stage4(S->Agt[0], Ag_w);
    stage4(S->Agt[1], Ag_w + 64 * 64);

#pragma unroll 1
    for (int i = tid; i < 2 * ROWS * ROWF; i += NTHREADS) {
        (&S->sW[0][0][0])[i] = 0.f;
        (&S->sI[0][0][0])[i] = 0.f;
        (&S->sA[0][0][0])[i] = 0.f;
    }

    // ---- mapping: warp = (rh, jg) ; lane = (kh in 0..3, jj in 0..7)
    const int lane = tid & 31, w = tid >> 5;
    const int jg = w & 7, rh = w >> 3;
    const int jj = lane & 7, kh = lane >> 3;
    const int j = jg * 8 + jj;
    const int js = j + ((j >> 4) << 2);   // skew 4 floats per 16
    const int R = rh * 4;                 // this group's first row
    const int khq = kh * 4;               // weight quad base (4 quads = 16 k)
    const int khf = kh * 20;              // state float base (skewed)
    const int bid = rh + 1;               // named barrier id
    const int ltid = tid & 255;           // tid within group
    const long base = (long)blockIdx.x * ROWS;

    float we[8];
#pragma unroll
    for (int s = 0; s < 8; s++) we[s] = we_w[s * 64 + j];
    const float be = we_b[j], bg = Wg_b[j], bz = Iz_b[j],
                br = Ir_b[j], bh = Ih_b[j], ba = Ag_b[j];

    // Phase-5: first 4 warps of each group; warp -> row R+(w&3)
    const int gw = w & 7;
    const int wrow = R + (gw & 3);
    const int o5 = lane & 3, seg = lane >> 2;
    float ph[8];
#pragma unroll
    for (int kk = 0; kk < 8; kk++) ph[kk] = phi_w[(seg * 8 + kk) * 4 + o5];
    const float bphi = phi_b[o5];
    const int segoff = seg * 8 + ((seg * 8) >> 4) * 4; // skewed offset

    // x staging: first 32 threads of each group stage its 4 rows
    const int xrow = R + (ltid >> 3), xc = ltid & 7;
    const float* xptr = x + (base + xrow) * (TT * SDIM) + xc;
    float xv = (ltid < 32) ? xptr[0] : 0.f;
    __syncthreads();
    if (ltid < 32) S->xs[xrow][xc] = xv;
    __syncthreads();

    for (int t = 0; t < TT; t++) {
        const int nb = t & 1, pb = nb ^ 1;
        if (ltid < 32 && t + 1 < TT) xv = xptr[(t + 1) * SDIM];

        const ulonglong2 *pw[4], *pi[4], *pa[4];
#pragma unroll
        for (int r = 0; r < 4; r++) {
            pw[r] = (const ulonglong2*)(S->sW[pb][R + r] + khf);
            pi[r] = (const ulonglong2*)(S->sI[pb][R + r] + khf);
            pa[r] = (const ulonglong2*)(S->sA[pb][R + r] + khf);
        }

        // ---------- Phase 1: encoder + W gate + W_in ----------
        float enc[4];
#pragma unroll
        for (int r = 0; r < 4; r++) {
            const float4* x4 = reinterpret_cast<const float4*>(S->xs[R + r]);
            float4 a = x4[0], b = x4[1];
            float e = be;
            e = fmaf(a.x, we[0], e); e = fmaf(a.y, we[1], e);
            e = fmaf(a.z, we[2], e); e = fmaf(a.w, we[3], e);
            e = fmaf(b.x, we[4], e); e = fmaf(b.y, we[5], e);
            e = fmaf(b.z, we[6], e); e = fmaf(b.w, we[7], e);
            enc[r] = tanh_f(e);
        }
        {
            ull aW[4][2] = {}, aG[4][2] = {};
#pragma unroll
            for (int q = 0; q < 4; q++) {
                const int qw = khq + q;
                uint2 m0 = S->Wff[0][qw][j]; ull m0x = h2f2(m0.x), m0y = h2f2(m0.y);
                uint2 m1 = S->Wff[1][qw][j]; ull m1x = h2f2(m1.x), m1y = h2f2(m1.y);
                uint2 m2 = S->Wff[2][qw][j]; ull m2x = h2f2(m2.x), m2y = h2f2(m2.y);
                uint2 u0 = S->Wg[0][qw][j];  ull u0x = h2f2(u0.x), u0y = h2f2(u0.y);
                uint2 u1 = S->Wg[1][qw][j];  ull u1x = h2f2(u1.x), u1y = h2f2(u1.y);
#pragma unroll
                for (int r = 0; r < 4; r++) {
                    ulonglong2 vw = pw[r][q], vi = pi[r][q], va = pa[r][q];
                    fma2(aW[r][0], m0x, vw.x); fma2(aW[r][1], m0y, vw.y);
                    fma2(aW[r][0], m1x, vi.x); fma2(aW[r][1], m1y, vi.y);
                    fma2(aG[r][0], u0x, vi.x); fma2(aG[r][1], u0y, vi.y);
                    fma2(aW[r][0], m2x, va.x); fma2(aW[r][1], m2y, va.y);
                    fma2(aG[r][0], u1x, va.x); fma2(aG[r][1], u1y, va.y);
                }
            }
#pragma unroll
            for (int r = 0; r < 4; r++) {
                float win = red16(aW[r][0], aW[r][1]);
                float gin = red16(aG[r][0], aG[r][1]);
                float Wn = tanh_f(enc[r] + win) * sigm_f(bg + gin);
                if (kh == 0) S->sW[nb][R + r][js] = Wn;
            }
        }
        gbar(bid);

        const ulonglong2* pwn[4];
#pragma unroll
        for (int r = 0; r < 4; r++)
            pwn[r] = (const ulonglong2*)(S->sW[nb][R + r] + khf);

        // ---------- Phase 2: z, r gates; stash r*I ----------
        float zv[4], Iold[4];
        {
            ull aZ[4][2] = {}, aR[4][2] = {};
#pragma unroll
            for (int q = 0; q < 4; q++) {
                const int qw = khq + q;
                uint2 za = S->Iz[0][qw][j]; ull zax = h2f2(za.x), zay = h2f2(za.y);
                uint2 zb = S->Iz[1][qw][j]; ull zbx = h2f2(zb.x), zby = h2f2(zb.y);
                uint2 zc = S->Iz[2][qw][j]; ull zcx = h2f2(zc.x), zcy = h2f2(zc.y);
                uint2 ra = S->Ir[0][qw][j]; ull rax = h2f2(ra.x), ray = h2f2(ra.y);
                uint2 rb = S->Ir[1][qw][j]; ull rbx = h2f2(rb.x), rby = h2f2(rb.y);
                uint2 rc = S->Ir[2][qw][j]; ull rcx = h2f2(rc.x), rcy = h2f2(rc.y);
#pragma unroll
                for (int r = 0; r < 4; r++) {
                    ulonglong2 vw = pwn[r][q], vi = pi[r][q], va = pa[r][q];
                    fma2(aZ[r][0], zax, vw.x); fma2(aZ[r][1], zay, vw.y);
                    fma2(aR[r][0], rax, vw.x); fma2(aR[r][1], ray, vw.y);
                    fma2(aZ[r][0], zbx, vi.x); fma2(aZ[r][1], zby, vi.y);
                    fma2(aR[r][0], rbx, vi.x); fma2(aR[r][1], rby, vi.y);
                    fma2(aZ[r][0], zcx, va.x); fma2(aZ[r][1], zcy, va.y);
                    fma2(aR[r][0], rcx, va.x); fma2(aR[r][1], rcy, va.y);
                }
            }
#pragma unroll
            for (int r = 0; r < 4; r++) {
                zv[r] = sigm_f(bz + red16(aZ[r][0], aZ[r][1]));
                float rv = sigm_f(br + red16(aR[r][0], aR[r][1]));
                Iold[r] = S->sI[pb][R + r][js];
                if (kh == 0) S->sRI[R + r][js] = rv * Iold[r];
            }
        }
        gbar(bid);

        // ---------- Phase 3: h, I_new ----------
        {
            const ulonglong2* pri[4];
#pragma unroll
            for (int r = 0; r < 4; r++)
                pri[r] = (const ulonglong2*)(S->sRI[R + r] + khf);
            ull aH[4][2] = {};
#pragma unroll
            for (int q = 0; q < 4; q++) {
                const int qw = khq + q;
                uint2 ha = S->Ih[0][qw][j]; ull hax = h2f2(ha.x), hay = h2f2(ha.y);
                uint2 hb = S->Ih[1][qw][j]; ull hbx = h2f2(hb.x), hby = h2f2(hb.y);
                uint2 hc = S->Ih[2][qw][j]; ull hcx = h2f2(hc.x), hcy = h2f2(hc.y);
#pragma unroll
                for (int r = 0; r < 4; r++) {
                    ulonglong2 vw = pwn[r][q], vq = pri[r][q], va = pa[r][q];
                    fma2(aH[r][0], hax, vw.x); fma2(aH[r][1], hay, vw.y);
                    fma2(aH[r][0], hbx, vq.x); fma2(aH[r][1], hby, vq.y);
                    fma2(aH[r][0], hcx, va.x); fma2(aH[r][1], hcy, va.y);
                }
            }
#pragma unroll
            for (int r = 0; r < 4; r++) {
                float h = tanh_f(bh + red16(aH[r][0], aH[r][1]));
                float In = (1.f - zv[r]) * Iold[r] + zv[r] * h;
                if (kh == 0) S->sI[nb][R + r][js] = In;
            }
        }
        gbar(bid);

        // ---------- Phase 4: A gate + A_in -> A_new ----------
        {
            const ulonglong2* pin[4];
#pragma unroll
            for (int r = 0; r < 4; r++)
                pin[r] = (const ulonglong2*)(S->sI[nb][R + r] + khf);
            ull aA[4][2] = {}, aC[4][2] = {};
#pragma unroll
            for (int q = 0; q < 4; q++) {
                const int qw = khq + q;
                uint2 fa = S->Aff[0][qw][j]; ull fax = h2f2(fa.x), fay = h2f2(fa.y);
                uint2 fb = S->Aff[1][qw][j]; ull fbx = h2f2(fb.x), fby = h2f2(fb.y);
                uint2 fc = S->Aff[2][qw][j]; ull fcx = h2f2(fc.x), fcy = h2f2(fc.y);
                uint2 ga = S->Agt[0][qw][j]; ull gax = h2f2(ga.x), gay = h2f2(ga.y);
                uint2 gb = S->Agt[1][qw][j]; ull gbx = h2f2(gb.x), gby = h2f2(gb.y);
#pragma unroll
                for (int r = 0; r < 4; r++) {
                    ulonglong2 vw = pwn[r][q], vi = pin[r][q], va = pa[r][q];
                    fma2(aA[r][0], fax, vw.x); fma2(aA[r][1], fay, vw.y);
                    fma2(aC[r][0], gax, vw.x); fma2(aC[r][1], gay, vw.y);
                    fma2(aA[r][0], fbx, vi.x); fma2(aA[r][1], fby, vi.y);
                    fma2(aC[r][0], gbx, vi.x); fma2(aC[r][1], gby, vi.y);
                    fma2(aA[r][0], fcx, va.x); fma2(aA[r][1], fcy, va.y);
                }
            }
#pragma unroll
            for (int r = 0; r < 4; r++) {
                float ain = red16(aA[r][0], aA[r][1]);
                float gin = red16(aC[r][0], aC[r][1]);
                float An = tanh_f(ain) * sigm_f(ba + gin);
                if (kh == 0) S->sA[nb][R + r][js] = An;
            }
        }
        if (ltid < 32) S->xs[xrow][xc] = xv;   // stage x for t+1 (group rows)
        gbar(bid);

        // ---------- Phase 5: action = A_new @ phi + b ----------
        if (gw < 4) {
            const float* arow = S->sA[nb][wrow] + segoff;
            float4 v0 = *reinterpret_cast<const float4*>(arow);
            float4 v1 = *reinterpret_cast<const float4*>(arow + 4);
            float p = v0.x * ph[0];
            p = fmaf(v0.y, ph[1], p);
            p = fmaf(v0.z, ph[2], p);
            p = fmaf(v0.w, ph[3], p);
            p = fmaf(v1.x, ph[4], p);
            p = fmaf(v1.y, ph[5], p);
            p = fmaf(v1.z, ph[6], p);
            p = fmaf(v1.w, ph[7], p);
            p += __shfl_down_sync(0xffffffffu, p, 16);
            p += __shfl_down_sync(0xffffffffu, p, 8);
            p += __shfl_down_sync(0xffffffffu, p, 4);
            if (lane < 4)
                out[(base + wrow) * (TT * ODIM) + t * ODIM + o5] = p + bphi;
        }
    }
}

extern "C" void kernel_launch(void* const* d_in, const int* in_sizes, int n_in,
                              void* d_out, int out_size) {
    (void)in_sizes; (void)n_in; (void)out_size;
    const size_t shmem = sizeof(Smem);
    cudaFuncSetAttribute(anima_kernel,
                         cudaFuncAttributeMaxDynamicSharedMemorySize,
                         (int)shmem);
    anima_kernel<<<NCTA, NTHREADS, shmem>>>(
        (const float*)d_in[0],
        (const float*)d_in[1], (const float*)d_in[2],
        (const float*)d_in[3], (const float*)d_in[4], (const float*)d_in[5],
        (const float*)d_in[6], (const float*)d_in[7],
        (const float*)d_in[8], (const float*)d_in[9],
        (const float*)d_in[10], (const float*)d_in[11],
        (const float*)d_in[12], (const float*)d_in[13],
        (const float*)d_in[14], (const float*)d_in[15], (const float*)d_in[16],
        (const float*)d_in[17], (const float*)d_in[18],
        (const float*)d_in[19], (const float*)d_in[20],
        (float*)d_out);
}

// round 11
// speedup vs baseline: 1.1035x; 1.1035x over previous
#include <cuda_runtime.h>
#include <cuda_fp16.h>

#define TT 512
#define SDIM 8
#define ODIM 4
#define NTHREADS 512
#define NCTA 128
#define ROWS 8
#define ROWF 80   // 4 kh-segments of 16 floats, 4-float skew between segments

typedef unsigned long long ull;

// fp16 weights as uint2 quads, CONSUMER-ORDERED:
// arr[q][jg][lane] with lane = kh*8+jj holds k-quad (4*(kh*4+q)..+3) of column j=jg*8+jj.
// A warp (fixed jg) at iteration q loads arr[q][jg][lane] -> contiguous 256B.
struct __align__(16) Smem {
    uint2 Wff[3][4][8][32];   // W_from_W, W_from_I, W_from_A
    uint2 Wg[2][4][8][32];    // W_gate rows [I | A]
    uint2 Iz[3][4][8][32];
    uint2 Ir[3][4][8][32];
    uint2 Ih[3][4][8][32];    // rows [Wn | r*I | A]
    uint2 Aff[3][4][8][32];
    uint2 Agt[2][4][8][32];   // rows [Wn | In]
    float sW[2][ROWS][ROWF];  // double-buffered states, skewed rows
    float sI[2][ROWS][ROWF];
    float sA[2][ROWS][ROWF];
    float sRI[ROWS][ROWF];
    float xs[ROWS][SDIM];
};

extern __shared__ char smem_raw[];

__device__ __forceinline__ float tanh_f(float x) {
    x = fminf(fmaxf(x, -9.0f), 9.0f);
    float e = __expf(2.0f * x);
    return __fdividef(e - 1.0f, e + 1.0f);
}
__device__ __forceinline__ float sigm_f(float x) {
    return __fdividef(1.0f, 1.0f + __expf(-x));
}

__device__ __forceinline__ ull h2f2(unsigned int h) {
    ull r;
    asm("{\n\t"
        ".reg .b16 l16, h16;\n\t"
        ".reg .f32 fl, fh;\n\t"
        "mov.b32 {l16, h16}, %1;\n\t"
        "cvt.f32.f16 fl, l16;\n\t"
        "cvt.f32.f16 fh, h16;\n\t"
        "mov.b64 %0, {fl, fh};\n\t"
        "}" : "=l"(r) : "r"(h));
    return r;
}
__device__ __forceinline__ void fma2(ull& d, ull a, ull b) {
    asm("fma.rn.f32x2 %0, %1, %2, %0;" : "+l"(d) : "l"(a), "l"(b));
}
__device__ __forceinline__ float hsum2(ull a, ull b) {
    float ax, ay, bx, by;
    asm("mov.b64 {%0, %1}, %2;" : "=f"(ax), "=f"(ay) : "l"(a));
    asm("mov.b64 {%0, %1}, %2;" : "=f"(bx), "=f"(by) : "l"(b));
    return (ax + bx) + (ay + by);
}
// 16-k partial -> full 64-k dot: reduce across kh (lane bits 3,4)
__device__ __forceinline__ float red16(ull P, ull Q) {
    float p = hsum2(P, Q);
    p += __shfl_xor_sync(0xffffffffu, p, 8);
    p += __shfl_xor_sync(0xffffffffu, p, 16);
    return p;
}
// group barrier: 256 threads of row-half group (barrier id 1 or 2)
__device__ __forceinline__ void gbar(int id) {
    asm volatile("bar.sync %0, 256;" :: "r"(id) : "memory");
}

// stage one 64x64 matrix into consumer-ordered fp16 quads
__device__ __forceinline__ void stage4(uint2 (&dst)[4][8][32],
                                       const float* __restrict__ src) {
#pragma unroll 1
    for (int i = threadIdx.x; i < 1024; i += NTHREADS) {
        int qg = i >> 6, j = i & 63;          // qg = global quad (k/4), j = column
        int q = qg & 3, kh = qg >> 2;
        int jgl = j >> 3, jj = j & 7;
        __half2 a = __floats2half2_rn(src[(4 * qg + 0) * 64 + j],
                                      src[(4 * qg + 1) * 64 + j]);
        __half2 b = __floats2half2_rn(src[(4 * qg + 2) * 64 + j],
                                      src[(4 * qg + 3) * 64 + j]);
        uint2 v;
        v.x = *reinterpret_cast<unsigned int*>(&a);
        v.y = *reinterpret_cast<unsigned int*>(&b);
        dst[q][jgl][kh * 8 + jj] = v;
    }
}

__global__ void __launch_bounds__(NTHREADS, 1)
anima_kernel(const float* __restrict__ x,
             const float* __restrict__ we_w, const float* __restrict__ we_b,
             const float* __restrict__ WfW, const float* __restrict__ WfI,
             const float* __restrict__ WfA,
             const float* __restrict__ Wg_w, const float* __restrict__ Wg_b,
             const float* __restrict__ Iz_w, const float* __restrict__ Iz_b,
             const float* __restrict__ Ir_w, const float* __restrict__ Ir_b,
             const float* __restrict__ Ih_w, const float* __restrict__ Ih_b,
             const float* __restrict__ AfW, const float* __restrict__ AfI,
             const float* __restrict__ AfA,
             const float* __restrict__ Ag_w, const float* __restrict__ Ag_b,
             const float* __restrict__ phi_w, const float* __restrict__ phi_b,
             float* __restrict__ out) {
    Smem* S = reinterpret_cast<Smem*>(smem_raw);
    const int tid = threadIdx.x;

    // ---- one-time staging
    stage4(S->Wff[0], WfW);
    stage4(S->Wff[1], WfI);
    stage4(S->Wff[2], WfA);
    stage4(S->Wg[0], Wg_w);
    stage4(S->Wg[1], Wg_w + 64 * 64);
    stage4(S->Iz[0], Iz_w);
    stage4(S->Iz[1], Iz_w + 64 * 64);
    stage4(S->Iz[2], Iz_w + 128 * 64);
    stage4(S->Ir[0], Ir_w);
    stage4(S->Ir[1], Ir_w + 64 * 64);
    stage4(S->Ir[2], Ir_w + 128 * 64);
    stage4(S->Ih[0], Ih_w);
    stage4(S->Ih[1], Ih_w + 64 * 64);
    stage4(S->Ih[2], Ih_w + 128 * 64);
    stage4(S->Aff[0], AfW);
    stage4(S->Aff[1], AfI);
    stage4(S->Aff[2], AfA);
    stage4(S->Agt[0], Ag_w);
    stage4(S->Agt[1], Ag_w + 64 * 64);

#pragma unroll 1
    for (int i = tid; i < 2 * ROWS * ROWF; i += NTHREADS) {
        (&S->sW[0][0][0])[i] = 0.f;
        (&S->sI[0][0][0])[i] = 0.f;
        (&S->sA[0][0][0])[i] = 0.f;
    }

    // ---- mapping: warp = (rh, jg) ; lane = (kh in 0..3, jj in 0..7)
    const int lane = tid & 31, w = tid >> 5;
    const int jg = w & 7, rh = w >> 3;
    const int jj = lane & 7, kh = lane >> 3;
    const int j = jg * 8 + jj;
    const int js = j + ((j >> 4) << 2);   // skew 4 floats per 16
    const int R = rh * 4;                 // this group's first row
    const int khf = kh * 20;              // state float base (skewed)
    const int bid = rh + 1;               // named barrier id
    const int ltid = tid & 255;           // tid within group
    const long base = (long)blockIdx.x * ROWS;

    float we[8];
#pragma unroll
    for (int s = 0; s < 8; s++) we[s] = we_w[s * 64 + j];
    const float be = we_b[j], bg = Wg_b[j], bz = Iz_b[j],
                br = Ir_b[j], bh = Ih_b[j], ba = Ag_b[j];

    // Phase-5: first 4 warps of each group; warp -> row R+(w&3)
    const int gw = w & 7;
    const int wrow = R + (gw & 3);
    const int o5 = lane & 3, seg = lane >> 2;
    float ph[8];
#pragma unroll
    for (int kk = 0; kk < 8; kk++) ph[kk] = phi_w[(seg * 8 + kk) * 4 + o5];
    const float bphi = phi_b[o5];
    const int segoff = seg * 8 + ((seg * 8) >> 4) * 4; // skewed offset

    // x staging: first 32 threads of each group stage its 4 rows
    const int xrow = R + (ltid >> 3), xc = ltid & 7;
    const float* xptr = x + (base + xrow) * (TT * SDIM) + xc;
    float xv = (ltid < 32) ? xptr[0] : 0.f;
    __syncthreads();
    if (ltid < 32) S->xs[xrow][xc] = xv;
    __syncthreads();

    for (int t = 0; t < TT; t++) {
        const int nb = t & 1, pb = nb ^ 1;
        if (ltid < 32 && t + 1 < TT) xv = xptr[(t + 1) * SDIM];

        const ulonglong2 *pw[4], *pi[4], *pa[4];
#pragma unroll
        for (int r = 0; r < 4; r++) {
            pw[r] = (const ulonglong2*)(S->sW[pb][R + r] + khf);
            pi[r] = (const ulonglong2*)(S->sI[pb][R + r] + khf);
            pa[r] = (const ulonglong2*)(S->sA[pb][R + r] + khf);
        }

        // ---------- Phase 1: encoder + W gate + W_in ----------
        float enc[4];
#pragma unroll
        for (int r = 0; r < 4; r++) {
            const float4* x4 = reinterpret_cast<const float4*>(S->xs[R + r]);
            float4 a = x4[0], b = x4[1];
            float e = be;
            e = fmaf(a.x, we[0], e); e = fmaf(a.y, we[1], e);
            e = fmaf(a.z, we[2], e); e = fmaf(a.w, we[3], e);
            e = fmaf(b.x, we[4], e); e = fmaf(b.y, we[5], e);
            e = fmaf(b.z, we[6], e); e = fmaf(b.w, we[7], e);
            enc[r] = tanh_f(e);
        }
        {
            ull aW[4][2] = {}, aG[4][2] = {};
#pragma unroll
            for (int q = 0; q < 4; q++) {
                uint2 m0 = S->Wff[0][q][jg][lane]; ull m0x = h2f2(m0.x), m0y = h2f2(m0.y);
                uint2 m1 = S->Wff[1][q][jg][lane]; ull m1x = h2f2(m1.x), m1y = h2f2(m1.y);
                uint2 m2 = S->Wff[2][q][jg][lane]; ull m2x = h2f2(m2.x), m2y = h2f2(m2.y);
                uint2 u0 = S->Wg[0][q][jg][lane];  ull u0x = h2f2(u0.x), u0y = h2f2(u0.y);
                uint2 u1 = S->Wg[1][q][jg][lane];  ull u1x = h2f2(u1.x), u1y = h2f2(u1.y);
#pragma unroll
                for (int r = 0; r < 4; r++) {
                    ulonglong2 vw = pw[r][q], vi = pi[r][q], va = pa[r][q];
                    fma2(aW[r][0], m0x, vw.x); fma2(aW[r][1], m0y, vw.y);
                    fma2(aW[r][0], m1x, vi.x); fma2(aW[r][1], m1y, vi.y);
                    fma2(aG[r][0], u0x, vi.x); fma2(aG[r][1], u0y, vi.y);
                    fma2(aW[r][0], m2x, va.x); fma2(aW[r][1], m2y, va.y);
                    fma2(aG[r][0], u1x, va.x); fma2(aG[r][1], u1y, va.y);
                }
            }
#pragma unroll
            for (int r = 0; r < 4; r++) {
                float win = red16(aW[r][0], aW[r][1]);
                float gin = red16(aG[r][0], aG[r][1]);
                float Wn = tanh_f(enc[r] + win) * sigm_f(bg + gin);
                if (kh == 0) S->sW[nb][R + r][js] = Wn;
            }
        }
        gbar(bid);

        const ulonglong2* pwn[4];
#pragma unroll
        for (int r = 0; r < 4; r++)
            pwn[r] = (const ulonglong2*)(S->sW[nb][R + r] + khf);

        // ---------- Phase 2: z, r gates; stash r*I ----------
        float zv[4], Iold[4];
        {
            ull aZ[4][2] = {}, aR[4][2] = {};
#pragma unroll
            for (int q = 0; q < 4; q++) {
                uint2 za = S->Iz[0][q][jg][lane]; ull zax = h2f2(za.x), zay = h2f2(za.y);
                uint2 zb = S->Iz[1][q][jg][lane]; ull zbx = h2f2(zb.x), zby = h2f2(zb.y);
                uint2 zc = S->Iz[2][q][jg][lane]; ull zcx = h2f2(zc.x), zcy = h2f2(zc.y);
                uint2 ra = S->Ir[0][q][jg][lane]; ull rax = h2f2(ra.x), ray = h2f2(ra.y);
                uint2 rb = S->Ir[1][q][jg][lane]; ull rbx = h2f2(rb.x), rby = h2f2(rb.y);
                uint2 rc = S->Ir[2][q][jg][lane]; ull rcx = h2f2(rc.x), rcy = h2f2(rc.y);
#pragma unroll
                for (int r = 0; r < 4; r++) {
                    ulonglong2 vw = pwn[r][q], vi = pi[r][q], va = pa[r][q];
                    fma2(aZ[r][0], zax, vw.x); fma2(aZ[r][1], zay, vw.y);
                    fma2(aR[r][0], rax, vw.x); fma2(aR[r][1], ray, vw.y);
                    fma2(aZ[r][0], zbx, vi.x); fma2(aZ[r][1], zby, vi.y);
                    fma2(aR[r][0], rbx, vi.x); fma2(aR[r][1], rby, vi.y);
                    fma2(aZ[r][0], zcx, va.x); fma2(aZ[r][1], zcy, va.y);
                    fma2(aR[r][0], rcx, va.x); fma2(aR[r][1], rcy, va.y);
                }
            }
#pragma unroll
            for (int r = 0; r < 4; r++) {
                zv[r] = sigm_f(bz + red16(aZ[r][0], aZ[r][1]));
                float rv = sigm_f(br + red16(aR[r][0], aR[r][1]));
                Iold[r] = S->sI[pb][R + r][js];
                if (kh == 0) S->sRI[R + r][js] = rv * Iold[r];
            }
        }
        gbar(bid);

        // ---------- Phase 3: h, I_new ----------
        {
            const ulonglong2* pri[4];
#pragma unroll
            for (int r = 0; r < 4; r++)
                pri[r] = (const ulonglong2*)(S->sRI[R + r] + khf);
            ull aH[4][2] = {};
#pragma unroll
            for (int q = 0; q < 4; q++) {
                uint2 ha = S->Ih[0][q][jg][lane]; ull hax = h2f2(ha.x), hay = h2f2(ha.y);
                uint2 hb = S->Ih[1][q][jg][lane]; ull hbx = h2f2(hb.x), hby = h2f2(hb.y);
                uint2 hc = S->Ih[2][q][jg][lane]; ull hcx = h2f2(hc.x), hcy = h2f2(hc.y);
#pragma unroll
                for (int r = 0; r < 4; r++) {
                    ulonglong2 vw = pwn[r][q], vq = pri[r][q], va = pa[r][q];
                    fma2(aH[r][0], hax, vw.x); fma2(aH[r][1], hay, vw.y);
                    fma2(aH[r][0], hbx, vq.x); fma2(aH[r][1], hby, vq.y);
                    fma2(aH[r][0], hcx, va.x); fma2(aH[r][1], hcy, va.y);
                }
            }
#pragma unroll
            for (int r = 0; r < 4; r++) {
                float h = tanh_f(bh + red16(aH[r][0], aH[r][1]));
                float In = (1.f - zv[r]) * Iold[r] + zv[r] * h;
                if (kh == 0) S->sI[nb][R + r][js] = In;
            }
        }
        gbar(bid);

        // ---------- Phase 4: A gate + A_in -> A_new ----------
        {
            const ulonglong2* pin[4];
#pragma unroll
            for (int r = 0; r < 4; r++)
                pin[r] = (const ulonglong2*)(S->sI[nb][R + r] + khf);
            ull aA[4][2] = {}, aC[4][2] = {};
#pragma unroll
            for (int q = 0; q < 4; q++) {
                uint2 fa = S->Aff[0][q][jg][lane]; ull fax = h2f2(fa.x), fay = h2f2(fa.y);
                uint2 fb = S->Aff[1][q][jg][lane]; ull fbx = h2f2(fb.x), fby = h2f2(fb.y);
                uint2 fc = S->Aff[2][q][jg][lane]; ull fcx = h2f2(fc.x), fcy = h2f2(fc.y);
                uint2 ga = S->Agt[0][q][jg][lane]; ull gax = h2f2(ga.x), gay = h2f2(ga.y);
                uint2 gb = S->Agt[1][q][jg][lane]; ull gbx = h2f2(gb.x), gby = h2f2(gb.y);
#pragma unroll
                for (int r = 0; r < 4; r++) {
                    ulonglong2 vw = pwn[r][q], vi = pin[r][q], va = pa[r][q];
                    fma2(aA[r][0], fax, vw.x); fma2(aA[r][1], fay, vw.y);
                    fma2(aC[r][0], gax, vw.x); fma2(aC[r][1], gay, vw.y);
                    fma2(aA[r][0], fbx, vi.x); fma2(aA[r][1], fby, vi.y);
                    fma2(aC[r][0], gbx, vi.x); fma2(aC[r][1], gby, vi.y);
                    fma2(aA[r][0], fcx, va.x); fma2(aA[r][1], fcy, va.y);
                }
            }
#pragma unroll
            for (int r = 0; r < 4; r++) {
                float ain = red16(aA[r][0], aA[r][1]);
                float gin = red16(aC[r][0], aC[r][1]);
                float An = tanh_f(ain) * sigm_f(ba + gin);
                if (kh == 0) S->sA[nb][R + r][js] = An;
            }
        }
        if (ltid < 32) S->xs[xrow][xc] = xv;   // stage x for t+1 (group rows)
        gbar(bid);

        // ---------- Phase 5: action = A_new @ phi + b ----------
        if (gw < 4) {
            const float* arow = S->sA[nb][wrow] + segoff;
            float4 v0 = *reinterpret_cast<const float4*>(arow);
            float4 v1 = *reinterpret_cast<const float4*>(arow + 4);
            float p = v0.x * ph[0];
            p = fmaf(v0.y, ph[1], p);
            p = fmaf(v0.z, ph[2], p);
            p = fmaf(v0.w, ph[3], p);
            p = fmaf(v1.x, ph[4], p);
            p = fmaf(v1.y, ph[5], p);
            p = fmaf(v1.z, ph[6], p);
            p = fmaf(v1.w, ph[7], p);
            p += __shfl_down_sync(0xffffffffu, p, 16);
            p += __shfl_down_sync(0xffffffffu, p, 8);
            p += __shfl_down_sync(0xffffffffu, p, 4);
            if (lane < 4)
                out[(base + wrow) * (TT * ODIM) + t * ODIM + o5] = p + bphi;
        }
    }
}

extern "C" void kernel_launch(void* const* d_in, const int* in_sizes, int n_in,
                              void* d_out, int out_size) {
    (void)in_sizes; (void)n_in; (void)out_size;
    const size_t shmem = sizeof(Smem);
    cudaFuncSetAttribute(anima_kernel,
                         cudaFuncAttributeMaxDynamicSharedMemorySize,
                         (int)shmem);
    anima_kernel<<<NCTA, NTHREADS, shmem>>>(
        (const float*)d_in[0],
        (const float*)d_in[1], (const float*)d_in[2],
        (const float*)d_in[3], (const float*)d_in[4], (const float*)d_in[5],
        (const float*)d_in[6], (const float*)d_in[7],
        (const float*)d_in[8], (const float*)d_in[9],
        (const float*)d_in[10], (const float*)d_in[11],
        (const float*)d_in[12], (const float*)d_in[13],
        (const float*)d_in[14], (const float*)d_in[15], (const float*)d_in[16],
        (const float*)d_in[17], (const float*)d_in[18],
        (const float*)d_in[19], (const float*)d_in[20],
        (float*)d_out);
}

// round 12
// speedup vs baseline: 3.7016x; 3.3543x over previous
#include <cuda_runtime.h>
#include <cuda_fp16.h>
#include <cstdint>

#define TT 512
#define SDIM 8
#define ODIM 4
#define NTHREADS 256
#define NCTA 128

#define KP3 200   // padded row stride (halves) for 192-k weight blocks
#define KP2 136   // padded row stride for 128-k blocks
#define SSTR 264  // fp16 state row stride (halves): slots [W:0|I:64|A:128|RI:192]
#define GP  68    // fp32 temp row stride (floats)

struct __align__(16) Smem {
    __half win[64 * KP3];   // [j][ W|I|A ]      (W_from_*)
    __half wz [64 * KP3];   // [j][ Wn|I|A ]     (I_z)
    __half wr [64 * KP3];   // [j][ Wn|I|A ]     (I_r)
    __half wh [64 * KP3];   // [j][ Wn|rI|A ]    (I_h)
    __half wa [64 * KP3];   // [j][ Wn|In|A ]    (A_from_*)
    __half wg [64 * KP2];   // [j][ I|A ]        (W_gate)
    __half wag[64 * KP2];   // [j][ Wn|In ]      (A_gate)
    __half st [8 * SSTR];   // fp16 states per row: [W | I | A | RI]
    float gtmp[8 * GP];     // gate sigm (P1: Wg, P4: Ag)
    float ztmp[8 * GP];     // z
    float Ifp [8 * GP];     // fp32 master of I
    float xs[8][SDIM];
};

extern __shared__ char smem_raw[];

__device__ __forceinline__ float tanh_f(float x) {
    x = fminf(fmaxf(x, -9.0f), 9.0f);
    float e = __expf(2.0f * x);
    return __fdividef(e - 1.0f, e + 1.0f);
}
__device__ __forceinline__ float sigm_f(float x) {
    return __fdividef(1.0f, 1.0f + __expf(-x));
}
__device__ __forceinline__ uint32_t s2u(const void* p) {
    uint32_t a;
    asm("{ .reg .u64 t; cvta.to.shared.u64 t, %1; cvt.u32.u64 %0, t; }"
        : "=r"(a) : "l"(p));
    return a;
}
__device__ __forceinline__ void ldsm4(uint32_t addr, uint32_t& r0, uint32_t& r1,
                                      uint32_t& r2, uint32_t& r3) {
    asm volatile("ldmatrix.sync.aligned.m8n8.x4.shared.b16 {%0,%1,%2,%3}, [%4];"
                 : "=r"(r0), "=r"(r1), "=r"(r2), "=r"(r3) : "r"(addr));
}
__device__ __forceinline__ uint32_t lds32(uint32_t addr) {
    uint32_t v;
    asm volatile("ld.shared.b32 %0, [%1];" : "=r"(v) : "r"(addr));
    return v;
}
__device__ __forceinline__ void mma16816(float& d0, float& d1, float& d2, float& d3,
                                         uint32_t a0, uint32_t a1, uint32_t a2,
                                         uint32_t a3, uint32_t b0, uint32_t b1) {
    asm volatile(
        "mma.sync.aligned.m16n8k16.row.col.f32.f16.f16.f32 "
        "{%0,%1,%2,%3}, {%4,%5,%6,%7}, {%8,%9}, {%0,%1,%2,%3};"
        : "+f"(d0), "+f"(d1), "+f"(d2), "+f"(d3)
        : "r"(a0), "r"(a1), "r"(a2), "r"(a3), "r"(b0), "r"(b1));
}

// one (output, j-tile) unit: D[16j x 8rows] += A[16j x 16k] @ B[16k x 8rows] over NKT tiles
template <int NKT>
__device__ __forceinline__ void unit_lin(uint32_t ab, uint32_t bb, int bstart,
                                         float (&d)[4]) {
    float e[4] = {0.f, 0.f, 0.f, 0.f};
#pragma unroll
    for (int kt = 0; kt < NKT; kt++) {
        uint32_t a0, a1, a2, a3;
        ldsm4(ab + kt * 32, a0, a1, a2, a3);
        uint32_t b0 = lds32(bb + bstart + kt * 32);
        uint32_t b1 = lds32(bb + bstart + kt * 32 + 16);
        if (kt & 1) mma16816(e[0], e[1], e[2], e[3], a0, a1, a2, a3, b0, b1);
        else        mma16816(d[0], d[1], d[2], d[3], a0, a1, a2, a3, b0, b1);
    }
    d[0] += e[0]; d[1] += e[1]; d[2] += e[2]; d[3] += e[3];
}
// h unit: k-slots [W, RI, A] (byte offsets into state row)
__device__ __forceinline__ void unit_h(uint32_t ab, uint32_t bb, float (&d)[4]) {
    const int boff[12] = {0, 32, 64, 96, 384, 416, 448, 480, 256, 288, 320, 352};
    float e[4] = {0.f, 0.f, 0.f, 0.f};
#pragma unroll
    for (int kt = 0; kt < 12; kt++) {
        uint32_t a0, a1, a2, a3;
        ldsm4(ab + kt * 32, a0, a1, a2, a3);
        uint32_t b0 = lds32(bb + boff[kt]);
        uint32_t b1 = lds32(bb + boff[kt] + 16);
        if (kt & 1) mma16816(e[0], e[1], e[2], e[3], a0, a1, a2, a3, b0, b1);
        else        mma16816(d[0], d[1], d[2], d[3], a0, a1, a2, a3, b0, b1);
    }
    d[0] += e[0]; d[1] += e[1]; d[2] += e[2]; d[3] += e[3];
}

// stage [K x 64] fp32 global -> transposed fp16 smem block dst[j][koff + k]
__device__ __forceinline__ void stage_mat(__half* dst, int Kp, int koff,
                                          const float* __restrict__ src, int K) {
#pragma unroll 1
    for (int i = threadIdx.x; i < K * 64; i += NTHREADS) {
        int k = i >> 6, j = i & 63;
        dst[j * Kp + koff + k] = __float2half(src[i]);
    }
}

__global__ void __launch_bounds__(NTHREADS, 1)
anima_kernel(const float* __restrict__ x,
             const float* __restrict__ we_w, const float* __restrict__ we_b,
             const float* __restrict__ WfW, const float* __restrict__ WfI,
             const float* __restrict__ WfA,
             const float* __restrict__ Wg_w, const float* __restrict__ Wg_b,
             const float* __restrict__ Iz_w, const float* __restrict__ Iz_b,
             const float* __restrict__ Ir_w, const float* __restrict__ Ir_b,
             const float* __restrict__ Ih_w, const float* __restrict__ Ih_b,
             const float* __restrict__ AfW, const float* __restrict__ AfI,
             const float* __restrict__ AfA,
             const float* __restrict__ Ag_w, const float* __restrict__ Ag_b,
             const float* __restrict__ phi_w, const float* __restrict__ phi_b,
             float* __restrict__ out) {
    Smem* S = reinterpret_cast<Smem*>(smem_raw);
    const int tid = threadIdx.x;

    // ---- one-time staging (transposed, k-concatenated)
    stage_mat(S->win, KP3, 0, WfW, 64);
    stage_mat(S->win, KP3, 64, WfI, 64);
    stage_mat(S->win, KP3, 128, WfA, 64);
    stage_mat(S->wz, KP3, 0, Iz_w, 192);
    stage_mat(S->wr, KP3, 0, Ir_w, 192);
    stage_mat(S->wh, KP3, 0, Ih_w, 192);
    stage_mat(S->wa, KP3, 0, AfW, 64);
    stage_mat(S->wa, KP3, 64, AfI, 64);
    stage_mat(S->wa, KP3, 128, AfA, 64);
    stage_mat(S->wg, KP2, 0, Wg_w, 128);
    stage_mat(S->wag, KP2, 0, Ag_w, 128);

#pragma unroll 1
    for (int i = tid; i < 8 * SSTR / 2; i += NTHREADS)
        reinterpret_cast<uint32_t*>(S->st)[i] = 0u;
#pragma unroll 1
    for (int i = tid; i < 8 * GP; i += NTHREADS) S->Ifp[i] = 0.f;

    // ---- warp mapping
    const int lane = tid & 31, w = tid >> 5;
    const int half = w >> 2, jt = w & 3;
    const int g = lane >> 2, t = lane & 3;
    const int rl = (lane & 7) | (((lane >> 3) & 1) << 3);
    const int c8 = (lane >> 4) * 8;
    const int j1 = jt * 16 + g, j2 = j1 + 8;
    const int n0 = 2 * t, n1 = 2 * t + 1;
    const long base = (long)blockIdx.x * 8;

    const uint32_t arow3 = ((jt * 16 + rl) * KP3 + c8) * 2;
    const uint32_t arow2 = ((jt * 16 + rl) * KP2 + c8) * 2;
    const uint32_t aP1 = half ? s2u(S->wg) + arow2 : s2u(S->win) + arow3;
    const uint32_t aP2 = half ? s2u(S->wr) + arow3 : s2u(S->wz) + arow3;
    const uint32_t aP3 = s2u(S->wh) + arow3;
    const uint32_t aP4 = half ? s2u(S->wag) + arow2 : s2u(S->wa) + arow3;
    const uint32_t bb = s2u(S->st) + g * (SSTR * 2) + t * 4;

    // per-warp constants
    float we1[8], we2[8];
#pragma unroll
    for (int s = 0; s < 8; s++) {
        we1[s] = we_w[s * 64 + j1];
        we2[s] = we_w[s * 64 + j2];
    }
    const float be1 = we_b[j1], be2 = we_b[j2];
    const float bg1 = Wg_b[j1], bg2 = Wg_b[j2];
    const float bz1 = Iz_b[j1], bz2 = Iz_b[j2];
    const float br1 = Ir_b[j1], br2 = Ir_b[j2];
    const float bh1 = Ih_b[j1], bh2 = Ih_b[j2];
    const float ba1 = Ag_b[j1], ba2 = Ag_b[j2];

    // P5: warp = batch row, lane -> (o, k-seg)
    const int o5 = lane & 3, seg = lane >> 2;
    float ph[8];
#pragma unroll
    for (int kk = 0; kk < 8; kk++) ph[kk] = phi_w[(seg * 8 + kk) * 4 + o5];
    const float bphi = phi_b[o5];

    // x staging
    const int xrow = tid >> 3, xc = tid & 7;
    const float* xptr = x + (base + xrow) * (TT * SDIM) + xc;
    float xv = (tid < 64) ? xptr[0] : 0.f;
    __syncthreads();
    if (tid < 64) S->xs[xrow][xc] = xv;
    __syncthreads();
    if (tid < 64) xv = xptr[SDIM];

    for (int t_ = 0; t_ < TT; t_++) {
        // ================= P1: W_in (half0) / W_gate (half1) =================
        {
            float d[4] = {0.f, 0.f, 0.f, 0.f};
            if (half) {
                unit_lin<8>(aP1, bb, 128, d);   // k over [I|A] slots
                S->gtmp[n0 * GP + j1] = sigm_f(d[0] + bg1);
                S->gtmp[n1 * GP + j1] = sigm_f(d[1] + bg1);
                S->gtmp[n0 * GP + j2] = sigm_f(d[2] + bg2);
                S->gtmp[n1 * GP + j2] = sigm_f(d[3] + bg2);
            } else {
                unit_lin<12>(aP1, bb, 0, d);    // k over [W|I|A]
            }
            __syncthreads();                    // P1a: gate ready
            if (!half) {
                const float* x0 = S->xs[n0];
                const float* x1 = S->xs[n1];
                float e00 = be1, e10 = be1, e01 = be2, e11 = be2;
#pragma unroll
                for (int s = 0; s < 8; s++) {
                    e00 = fmaf(x0[s], we1[s], e00);
                    e10 = fmaf(x1[s], we1[s], e10);
                    e01 = fmaf(x0[s], we2[s], e01);
                    e11 = fmaf(x1[s], we2[s], e11);
                }
                float w00 = tanh_f(d[0] + tanh_f(e00)) * S->gtmp[n0 * GP + j1];
                float w10 = tanh_f(d[1] + tanh_f(e10)) * S->gtmp[n1 * GP + j1];
                float w01 = tanh_f(d[2] + tanh_f(e01)) * S->gtmp[n0 * GP + j2];
                float w11 = tanh_f(d[3] + tanh_f(e11)) * S->gtmp[n1 * GP + j2];
                S->st[n0 * SSTR + j1] = __float2half(w00);
                S->st[n1 * SSTR + j1] = __float2half(w10);
                S->st[n0 * SSTR + j2] = __float2half(w01);
                S->st[n1 * SSTR + j2] = __float2half(w11);
            }
        }
        __syncthreads();                        // P1b: W_new ready

        // ================= P2: z (half0) / r -> RI (half1) =================
        {
            float d[4] = {0.f, 0.f, 0.f, 0.f};
            if (half) {
                unit_lin<12>(aP2, bb, 0, d);    // r over [Wn|I|A]
                float r00 = sigm_f(d[0] + br1), r10 = sigm_f(d[1] + br1);
                float r01 = sigm_f(d[2] + br2), r11 = sigm_f(d[3] + br2);
                S->st[n0 * SSTR + 192 + j1] = __float2half(r00 * S->Ifp[n0 * GP + j1]);
                S->st[n1 * SSTR + 192 + j1] = __float2half(r10 * S->Ifp[n1 * GP + j1]);
                S->st[n0 * SSTR + 192 + j2] = __float2half(r01 * S->Ifp[n0 * GP + j2]);
                S->st[n1 * SSTR + 192 + j2] = __float2half(r11 * S->Ifp[n1 * GP + j2]);
            } else {
                unit_lin<12>(aP2, bb, 0, d);    // z over [Wn|I|A]
                S->ztmp[n0 * GP + j1] = sigm_f(d[0] + bz1);
                S->ztmp[n1 * GP + j1] = sigm_f(d[1] + bz1);
                S->ztmp[n0 * GP + j2] = sigm_f(d[2] + bz2);
                S->ztmp[n1 * GP + j2] = sigm_f(d[3] + bz2);
            }
        }
        __syncthreads();                        // P2 done (z, RI ready)

        // ================= P3: h -> I_new (half0 only) =================
        if (!half) {
            float d[4] = {0.f, 0.f, 0.f, 0.f};
            unit_h(aP3, bb, d);                 // [Wn | RI | A]
            float h00 = tanh_f(d[0] + bh1), h10 = tanh_f(d[1] + bh1);
            float h01 = tanh_f(d[2] + bh2), h11 = tanh_f(d[3] + bh2);
            float z00 = S->ztmp[n0 * GP + j1], z10 = S->ztmp[n1 * GP + j1];
            float z01 = S->ztmp[n0 * GP + j2], z11 = S->ztmp[n1 * GP + j2];
            float i00 = S->Ifp[n0 * GP + j1], i10 = S->Ifp[n1 * GP + j1];
            float i01 = S->Ifp[n0 * GP + j2], i11 = S->Ifp[n1 * GP + j2];
            float I00 = i00 + z00 * (h00 - i00);
            float I10 = i10 + z10 * (h10 - i10);
            float I01 = i01 + z01 * (h01 - i01);
            float I11 = i11 + z11 * (h11 - i11);
            S->Ifp[n0 * GP + j1] = I00; S->Ifp[n1 * GP + j1] = I10;
            S->Ifp[n0 * GP + j2] = I01; S->Ifp[n1 * GP + j2] = I11;
            S->st[n0 * SSTR + 64 + j1] = __float2half(I00);
            S->st[n1 * SSTR + 64 + j1] = __float2half(I10);
            S->st[n0 * SSTR + 64 + j2] = __float2half(I01);
            S->st[n1 * SSTR + 64 + j2] = __float2half(I11);
        }
        __syncthreads();                        // P3 done (I_new ready)

        // ================= P4: A_in (half0) / A_gate (half1) =================
        {
            float d[4] = {0.f, 0.f, 0.f, 0.f};
            if (half) {
                unit_lin<8>(aP4, bb, 0, d);     // Ag over [Wn|In]
                S->gtmp[n0 * GP + j1] = sigm_f(d[0] + ba1);
                S->gtmp[n1 * GP + j1] = sigm_f(d[1] + ba1);
                S->gtmp[n0 * GP + j2] = sigm_f(d[2] + ba2);
                S->gtmp[n1 * GP + j2] = sigm_f(d[3] + ba2);
            } else {
                unit_lin<12>(aP4, bb, 0, d);    // A_in over [Wn|In|A]
            }
            __syncthreads();                    // P4a: gate ready
            if (!half) {
                float a00 = tanh_f(d[0]) * S->gtmp[n0 * GP + j1];
                float a10 = tanh_f(d[1]) * S->gtmp[n1 * GP + j1];
                float a01 = tanh_f(d[2]) * S->gtmp[n0 * GP + j2];
                float a11 = tanh_f(d[3]) * S->gtmp[n1 * GP + j2];
                S->st[n0 * SSTR + 128 + j1] = __float2half(a00);
                S->st[n1 * SSTR + 128 + j1] = __float2half(a10);
                S->st[n0 * SSTR + 128 + j2] = __float2half(a01);
                S->st[n1 * SSTR + 128 + j2] = __float2half(a11);
            }
            if (tid < 64) S->xs[xrow][xc] = xv;  // x for t+1 (read in next P1)
        }
        __syncthreads();                        // P4b: A_new + x ready
        if (tid < 64 && t_ + 2 < TT) xv = xptr[(t_ + 2) * SDIM];

        // ================= P5: action = A_new @ phi + b (warp = row) =======
        {
            const uint4 v = *reinterpret_cast<const uint4*>(
                S->st + w * SSTR + 128 + seg * 8);
            const __half2* hv = reinterpret_cast<const __half2*>(&v);
            float2 f0 = __half22float2(hv[0]);
            float2 f1 = __half22float2(hv[1]);
            float2 f2 = __half22float2(hv[2]);
            float2 f3 = __half22float2(hv[3]);
            float p = f0.x * ph[0];
            p = fmaf(f0.y, ph[1], p);
            p = fmaf(f1.x, ph[2], p);
            p = fmaf(f1.y, ph[3], p);
            p = fmaf(f2.x, ph[4], p);
            p = fmaf(f2.y, ph[5], p);
            p = fmaf(f3.x, ph[6], p);
            p = fmaf(f3.y, ph[7], p);
            p += __shfl_down_sync(0xffffffffu, p, 16);
            p += __shfl_down_sync(0xffffffffu, p, 8);
            p += __shfl_down_sync(0xffffffffu, p, 4);
            if (lane < 4)
                out[(base + w) * (TT * ODIM) + t_ * ODIM + o5] = p + bphi;
        }
    }
}

extern "C" void kernel_launch(void* const* d_in, const int* in_sizes, int n_in,
                              void* d_out, int out_size) {
    (void)in_sizes; (void)n_in; (void)out_size;
    const size_t shmem = sizeof(Smem);
    cudaFuncSetAttribute(anima_kernel,
                         cudaFuncAttributeMaxDynamicSharedMemorySize,
                         (int)shmem);
    anima_kernel<<<NCTA, NTHREADS, shmem>>>(
        (const float*)d_in[0],
        (const float*)d_in[1], (const float*)d_in[2],
        (const float*)d_in[3], (const float*)d_in[4], (const float*)d_in[5],
        (const float*)d_in[6], (const float*)d_in[7],
        (const float*)d_in[8], (const float*)d_in[9],
        (const float*)d_in[10], (const float*)d_in[11],
        (const float*)d_in[12], (const float*)d_in[13],
        (const float*)d_in[14], (const float*)d_in[15], (const float*)d_in[16],
        (const float*)d_in[17], (const float*)d_in[18],
        (const float*)d_in[19], (const float*)d_in[20],
        (float*)d_out);
}

// round 13
// speedup vs baseline: 5.4697x; 1.4777x over previous
#include <cuda_runtime.h>
#include <cuda_fp16.h>
#include <cstdint>

#define TT 512
#define SDIM 8
#define ODIM 4
#define NTHREADS 256
#define NCTA 128

#define KP3 200   // padded row stride (halves) for 192-k weight blocks
#define KP2 136   // padded row stride for 128-k blocks
#define SSTR 264  // fp16 state row stride (halves): [W:0|I:64|A:128|RI:192]
#define GP  68    // fp32 temp row stride (floats)

struct __align__(16) Smem {
    __half win[64 * KP3];   // [j][ W|I|A ]   (W_from_*)
    __half wz [64 * KP3];   // [j][ Wn|I|A ]  (I_z)
    __half wr [64 * KP3];   // [j][ Wn|I|A ]  (I_r)
    __half wh [64 * KP3];   // [j][ Wn|rI|A ] (I_h)
    __half wa [64 * KP3];   // [j][ Wn|In|A ] (A_from_*)
    __half wg [64 * KP2];   // [j][ I|A ]     (W_gate)
    __half wag[64 * KP2];   // [j][ Wn|In ]   (A_gate)
    __half st [8 * SSTR];   // fp16 states per row
    float gtmp[8 * GP];     // P1: Wg sigm, P4: Ag sigm
    float ztmp[8 * GP];     // z
    float Ifp [8 * GP];     // fp32 master of I
    float xs[8][SDIM];
};

extern __shared__ char smem_raw[];

__device__ __forceinline__ float tanh_f(float x) {
    x = fminf(fmaxf(x, -9.0f), 9.0f);
    float e = __expf(2.0f * x);
    return __fdividef(e - 1.0f, e + 1.0f);
}
__device__ __forceinline__ float sigm_f(float x) {
    return __fdividef(1.0f, 1.0f + __expf(-x));
}
__device__ __forceinline__ uint32_t s2u(const void* p) {
    uint32_t a;
    asm("{ .reg .u64 t; cvta.to.shared.u64 t, %1; cvt.u32.u64 %0, t; }"
        : "=r"(a) : "l"(p));
    return a;
}
__device__ __forceinline__ void ldsm4(uint32_t addr, uint32_t& r0, uint32_t& r1,
                                      uint32_t& r2, uint32_t& r3) {
    asm volatile("ldmatrix.sync.aligned.m8n8.x4.shared.b16 {%0,%1,%2,%3}, [%4];"
                 : "=r"(r0), "=r"(r1), "=r"(r2), "=r"(r3) : "r"(addr));
}
__device__ __forceinline__ uint32_t lds32(uint32_t addr) {
    uint32_t v;
    asm volatile("ld.shared.b32 %0, [%1];" : "=r"(v) : "r"(addr));
    return v;
}
__device__ __forceinline__ void mma16816(float& d0, float& d1, float& d2, float& d3,
                                         uint32_t a0, uint32_t a1, uint32_t a2,
                                         uint32_t a3, uint32_t b0, uint32_t b1) {
    asm volatile(
        "mma.sync.aligned.m16n8k16.row.col.f32.f16.f16.f32 "
        "{%0,%1,%2,%3}, {%4,%5,%6,%7}, {%8,%9}, {%0,%1,%2,%3};"
        : "+f"(d0), "+f"(d1), "+f"(d2), "+f"(d3)
        : "r"(a0), "r"(a1), "r"(a2), "r"(a3), "r"(b0), "r"(b1));
}

#define BARR() asm volatile("bar.sync 0, 256;" ::: "memory")

// mma over hoisted fragments; B from state rows (bstart in bytes), 4 accum sets
template <int NKT>
__device__ __forceinline__ void mma_frag(const uint32_t (&f)[NKT][4],
                                         uint32_t bb, int bstart, float (&d)[4]) {
    float a0[4] = {0.f, 0.f, 0.f, 0.f}, a1[4] = {0.f, 0.f, 0.f, 0.f};
    float a2[4] = {0.f, 0.f, 0.f, 0.f}, a3[4] = {0.f, 0.f, 0.f, 0.f};
#pragma unroll
    for (int kt = 0; kt < NKT; kt++) {
        uint32_t b0 = lds32(bb + bstart + kt * 32);
        uint32_t b1 = lds32(bb + bstart + kt * 32 + 16);
        float* acc = ((kt & 3) == 0) ? a0
                   : ((kt & 3) == 1) ? a1
                   : ((kt & 3) == 2) ? a2 : a3;
        mma16816(acc[0], acc[1], acc[2], acc[3],
                 f[kt][0], f[kt][1], f[kt][2], f[kt][3], b0, b1);
    }
#pragma unroll
    for (int i = 0; i < 4; i++) d[i] = (a0[i] + a1[i]) + (a2[i] + a3[i]);
}
// h unit: B k-slots [W, RI, A]
__device__ __forceinline__ void mma_h(const uint32_t (&f)[12][4], uint32_t bb,
                                      float (&d)[4]) {
    const int boff[12] = {0, 32, 64, 96, 384, 416, 448, 480, 256, 288, 320, 352};
    float a0[4] = {0.f, 0.f, 0.f, 0.f}, a1[4] = {0.f, 0.f, 0.f, 0.f};
    float a2[4] = {0.f, 0.f, 0.f, 0.f}, a3[4] = {0.f, 0.f, 0.f, 0.f};
#pragma unroll
    for (int kt = 0; kt < 12; kt++) {
        uint32_t b0 = lds32(bb + boff[kt]);
        uint32_t b1 = lds32(bb + boff[kt] + 16);
        float* acc = ((kt & 3) == 0) ? a0
                   : ((kt & 3) == 1) ? a1
                   : ((kt & 3) == 2) ? a2 : a3;
        mma16816(acc[0], acc[1], acc[2], acc[3],
                 f[kt][0], f[kt][1], f[kt][2], f[kt][3], b0, b1);
    }
#pragma unroll
    for (int i = 0; i < 4; i++) d[i] = (a0[i] + a1[i]) + (a2[i] + a3[i]);
}

__device__ __forceinline__ void stage_mat(__half* dst, int Kp, int koff,
                                          const float* __restrict__ src, int K) {
#pragma unroll 1
    for (int i = threadIdx.x; i < K * 64; i += NTHREADS) {
        int k = i >> 6, j = i & 63;
        dst[j * Kp + koff + k] = __float2half(src[i]);
    }
}

__global__ void __launch_bounds__(NTHREADS, 1)
anima_kernel(const float* __restrict__ x,
             const float* __restrict__ we_w, const float* __restrict__ we_b,
             const float* __restrict__ WfW, const float* __restrict__ WfI,
             const float* __restrict__ WfA,
             const float* __restrict__ Wg_w, const float* __restrict__ Wg_b,
             const float* __restrict__ Iz_w, const float* __restrict__ Iz_b,
             const float* __restrict__ Ir_w, const float* __restrict__ Ir_b,
             const float* __restrict__ Ih_w, const float* __restrict__ Ih_b,
             const float* __restrict__ AfW, const float* __restrict__ AfI,
             const float* __restrict__ AfA,
             const float* __restrict__ Ag_w, const float* __restrict__ Ag_b,
             const float* __restrict__ phi_w, const float* __restrict__ phi_b,
             float* __restrict__ out) {
    Smem* S = reinterpret_cast<Smem*>(smem_raw);
    const int tid = threadIdx.x;

    // ---- one-time staging (transposed, k-concatenated)
    stage_mat(S->win, KP3, 0, WfW, 64);
    stage_mat(S->win, KP3, 64, WfI, 64);
    stage_mat(S->win, KP3, 128, WfA, 64);
    stage_mat(S->wz, KP3, 0, Iz_w, 192);
    stage_mat(S->wr, KP3, 0, Ir_w, 192);
    stage_mat(S->wh, KP3, 0, Ih_w, 192);
    stage_mat(S->wa, KP3, 0, AfW, 64);
    stage_mat(S->wa, KP3, 64, AfI, 64);
    stage_mat(S->wa, KP3, 128, AfA, 64);
    stage_mat(S->wg, KP2, 0, Wg_w, 128);
    stage_mat(S->wag, KP2, 0, Ag_w, 128);

#pragma unroll 1
    for (int i = tid; i < 8 * SSTR / 2; i += NTHREADS)
        reinterpret_cast<uint32_t*>(S->st)[i] = 0u;
#pragma unroll 1
    for (int i = tid; i < 8 * GP; i += NTHREADS) S->Ifp[i] = 0.f;

    // ---- common mapping
    const int lane = tid & 31, w = tid >> 5;
    const int jt = w & 3;
    const int g = lane >> 2, t4 = lane & 3;
    const int rl = (lane & 7) | (((lane >> 3) & 1) << 3);
    const int c8 = (lane >> 4) * 8;
    const int j1 = jt * 16 + g, j2 = j1 + 8;
    const int n0 = 2 * t4, n1 = n0 + 1;
    const long base = (long)blockIdx.x * 8;
    const uint32_t arow3 = ((jt * 16 + rl) * KP3 + c8) * 2;
    const uint32_t arow2 = ((jt * 16 + rl) * KP2 + c8) * 2;
    const uint32_t bb = s2u(S->st) + g * (SSTR * 2) + t4 * 4;

    // stage x(0)
    const int xrow = tid >> 3, xc = tid & 7;
    const float* xptr = x + (base + xrow) * (TT * SDIM) + xc;
    if (tid < 64) S->xs[xrow][xc] = xptr[0];
    __syncthreads();

    if (w < 4) {
        // ================= half0: W_in, z, A_in, encoder, P5, x =================
        uint32_t fW[12][4], fZ[12][4], fA[12][4];
        {
            const uint32_t aW_ = s2u(S->win) + arow3;
            const uint32_t aZ_ = s2u(S->wz) + arow3;
            const uint32_t aA_ = s2u(S->wa) + arow3;
#pragma unroll
            for (int kt = 0; kt < 12; kt++)
                ldsm4(aW_ + kt * 32, fW[kt][0], fW[kt][1], fW[kt][2], fW[kt][3]);
#pragma unroll
            for (int kt = 0; kt < 12; kt++)
                ldsm4(aZ_ + kt * 32, fZ[kt][0], fZ[kt][1], fZ[kt][2], fZ[kt][3]);
#pragma unroll
            for (int kt = 0; kt < 12; kt++)
                ldsm4(aA_ + kt * 32, fA[kt][0], fA[kt][1], fA[kt][2], fA[kt][3]);
        }
        float we1[8], we2[8];
#pragma unroll
        for (int s = 0; s < 8; s++) {
            we1[s] = we_w[s * 64 + j1];
            we2[s] = we_w[s * 64 + j2];
        }
        const float be1 = we_b[j1], be2 = we_b[j2];
        const float bz1 = Iz_b[j1], bz2 = Iz_b[j2];
        // P5: 2 rows per warp
        const int o5 = lane & 3, sg = (lane >> 2) & 3, rsel = lane >> 4;
        const int prow = w * 2 + rsel;
        float ph[16];
#pragma unroll
        for (int kk = 0; kk < 16; kk++) ph[kk] = phi_w[(sg * 16 + kk) * 4 + o5];
        const float bphi = phi_b[o5];
        float xv = (tid < 64) ? xptr[SDIM] : 0.f;

        for (int t_ = 0; t_ < TT; t_++) {
            float d[4];
            // ---- P1: W_in
            mma_frag<12>(fW, bb, 0, d);
            BARR();  // A: gtmp (Wg) ready
            {
                const float* x0 = S->xs[n0];
                const float* x1 = S->xs[n1];
                float e00 = be1, e10 = be1, e01 = be2, e11 = be2;
#pragma unroll
                for (int s = 0; s < 8; s++) {
                    e00 = fmaf(x0[s], we1[s], e00);
                    e10 = fmaf(x1[s], we1[s], e10);
                    e01 = fmaf(x0[s], we2[s], e01);
                    e11 = fmaf(x1[s], we2[s], e11);
                }
                float w00 = tanh_f(d[0] + tanh_f(e00)) * S->gtmp[n0 * GP + j1];
                float w10 = tanh_f(d[1] + tanh_f(e10)) * S->gtmp[n1 * GP + j1];
                float w01 = tanh_f(d[2] + tanh_f(e01)) * S->gtmp[n0 * GP + j2];
                float w11 = tanh_f(d[3] + tanh_f(e11)) * S->gtmp[n1 * GP + j2];
                S->st[n0 * SSTR + j1] = __float2half(w00);
                S->st[n1 * SSTR + j1] = __float2half(w10);
                S->st[n0 * SSTR + j2] = __float2half(w01);
                S->st[n1 * SSTR + j2] = __float2half(w11);
            }
            BARR();  // B: st[W] ready
            // ---- P2: z
            mma_frag<12>(fZ, bb, 0, d);
            S->ztmp[n0 * GP + j1] = sigm_f(d[0] + bz1);
            S->ztmp[n1 * GP + j1] = sigm_f(d[1] + bz1);
            S->ztmp[n0 * GP + j2] = sigm_f(d[2] + bz2);
            S->ztmp[n1 * GP + j2] = sigm_f(d[3] + bz2);
            BARR();  // C: ztmp + RI ready
            // ---- P3 window: P5(t-1) + x staging (h runs on half1)
            if (t_ > 0) {
                const __half* ap = S->st + prow * SSTR + 128 + sg * 16;
                uint4 v0 = *reinterpret_cast<const uint4*>(ap);
                uint4 v1 = *reinterpret_cast<const uint4*>(ap + 8);
                const __half2* h0 = reinterpret_cast<const __half2*>(&v0);
                const __half2* h1 = reinterpret_cast<const __half2*>(&v1);
                float p = 0.f;
#pragma unroll
                for (int q = 0; q < 4; q++) {
                    float2 f0 = __half22float2(h0[q]);
                    float2 f1 = __half22float2(h1[q]);
                    p = fmaf(f0.x, ph[2 * q], p);
                    p = fmaf(f0.y, ph[2 * q + 1], p);
                    p = fmaf(f1.x, ph[8 + 2 * q], p);
                    p = fmaf(f1.y, ph[9 + 2 * q], p);
                }
                p += __shfl_xor_sync(0xffffffffu, p, 4);
                p += __shfl_xor_sync(0xffffffffu, p, 8);
                if (sg == 0)
                    out[(base + prow) * (TT * ODIM) + (t_ - 1) * ODIM + o5] =
                        p + bphi;
            }
            if (tid < 64) {
                S->xs[xrow][xc] = xv;  // x(t+1)
                if (t_ + 2 < TT) xv = xptr[(t_ + 2) * SDIM];
            }
            BARR();  // D: st[I] ready
            // ---- P4: A_in
            mma_frag<12>(fA, bb, 0, d);
            BARR();  // E: gtmp (Ag) ready
            {
                float a00 = tanh_f(d[0]) * S->gtmp[n0 * GP + j1];
                float a10 = tanh_f(d[1]) * S->gtmp[n1 * GP + j1];
                float a01 = tanh_f(d[2]) * S->gtmp[n0 * GP + j2];
                float a11 = tanh_f(d[3]) * S->gtmp[n1 * GP + j2];
                S->st[n0 * SSTR + 128 + j1] = __float2half(a00);
                S->st[n1 * SSTR + 128 + j1] = __float2half(a10);
                S->st[n0 * SSTR + 128 + j2] = __float2half(a01);
                S->st[n1 * SSTR + 128 + j2] = __float2half(a11);
            }
            BARR();  // F: st[A] ready
        }
        // final P5 for t = TT-1
        {
            const __half* ap = S->st + prow * SSTR + 128 + sg * 16;
            uint4 v0 = *reinterpret_cast<const uint4*>(ap);
            uint4 v1 = *reinterpret_cast<const uint4*>(ap + 8);
            const __half2* h0 = reinterpret_cast<const __half2*>(&v0);
            const __half2* h1 = reinterpret_cast<const __half2*>(&v1);
            float p = 0.f;
#pragma unroll
            for (int q = 0; q < 4; q++) {
                float2 f0 = __half22float2(h0[q]);
                float2 f1 = __half22float2(h1[q]);
                p = fmaf(f0.x, ph[2 * q], p);
                p = fmaf(f0.y, ph[2 * q + 1], p);
                p = fmaf(f1.x, ph[8 + 2 * q], p);
                p = fmaf(f1.y, ph[9 + 2 * q], p);
            }
            p += __shfl_xor_sync(0xffffffffu, p, 4);
            p += __shfl_xor_sync(0xffffffffu, p, 8);
            if (sg == 0)
                out[(base + prow) * (TT * ODIM) + (TT - 1) * ODIM + o5] =
                    p + bphi;
        }
    } else {
        // ================= half1: Wg, r, h, Ag =================
        uint32_t fG[8][4], fR[12][4], fH[12][4], fAg[8][4];
        {
            const uint32_t aG_ = s2u(S->wg) + arow2;
            const uint32_t aR_ = s2u(S->wr) + arow3;
            const uint32_t aH_ = s2u(S->wh) + arow3;
            const uint32_t aAg_ = s2u(S->wag) + arow2;
#pragma unroll
            for (int kt = 0; kt < 8; kt++)
                ldsm4(aG_ + kt * 32, fG[kt][0], fG[kt][1], fG[kt][2], fG[kt][3]);
#pragma unroll
            for (int kt = 0; kt < 12; kt++)
                ldsm4(aR_ + kt * 32, fR[kt][0], fR[kt][1], fR[kt][2], fR[kt][3]);
#pragma unroll
            for (int kt = 0; kt < 12; kt++)
                ldsm4(aH_ + kt * 32, fH[kt][0], fH[kt][1], fH[kt][2], fH[kt][3]);
#pragma unroll
            for (int kt = 0; kt < 8; kt++)
                ldsm4(aAg_ + kt * 32, fAg[kt][0], fAg[kt][1], fAg[kt][2], fAg[kt][3]);
        }
        const float bg1 = Wg_b[j1], bg2 = Wg_b[j2];
        const float br1 = Ir_b[j1], br2 = Ir_b[j2];
        const float bh1 = Ih_b[j1], bh2 = Ih_b[j2];
        const float ba1 = Ag_b[j1], ba2 = Ag_b[j2];

        for (int t_ = 0; t_ < TT; t_++) {
            float d[4];
            // ---- P1: W gate (k over [I|A] = bytes 128..)
            mma_frag<8>(fG, bb, 128, d);
            S->gtmp[n0 * GP + j1] = sigm_f(d[0] + bg1);
            S->gtmp[n1 * GP + j1] = sigm_f(d[1] + bg1);
            S->gtmp[n0 * GP + j2] = sigm_f(d[2] + bg2);
            S->gtmp[n1 * GP + j2] = sigm_f(d[3] + bg2);
            BARR();  // A
            BARR();  // B: st[W] ready
            // ---- P2: r -> RI
            mma_frag<12>(fR, bb, 0, d);
            {
                float r00 = sigm_f(d[0] + br1), r10 = sigm_f(d[1] + br1);
                float r01 = sigm_f(d[2] + br2), r11 = sigm_f(d[3] + br2);
                S->st[n0 * SSTR + 192 + j1] =
                    __float2half(r00 * S->Ifp[n0 * GP + j1]);
                S->st[n1 * SSTR + 192 + j1] =
                    __float2half(r10 * S->Ifp[n1 * GP + j1]);
                S->st[n0 * SSTR + 192 + j2] =
                    __float2half(r01 * S->Ifp[n0 * GP + j2]);
                S->st[n1 * SSTR + 192 + j2] =
                    __float2half(r11 * S->Ifp[n1 * GP + j2]);
            }
            BARR();  // C: ztmp + RI ready
            // ---- P3: h -> I_new
            mma_h(fH, bb, d);
            {
                float h00 = tanh_f(d[0] + bh1), h10 = tanh_f(d[1] + bh1);
                float h01 = tanh_f(d[2] + bh2), h11 = tanh_f(d[3] + bh2);
                float z00 = S->ztmp[n0 * GP + j1], z10 = S->ztmp[n1 * GP + j1];
                float z01 = S->ztmp[n0 * GP + j2], z11 = S->ztmp[n1 * GP + j2];
                float i00 = S->Ifp[n0 * GP + j1], i10 = S->Ifp[n1 * GP + j1];
                float i01 = S->Ifp[n0 * GP + j2], i11 = S->Ifp[n1 * GP + j2];
                float I00 = i00 + z00 * (h00 - i00);
                float I10 = i10 + z10 * (h10 - i10);
                float I01 = i01 + z01 * (h01 - i01);
                float I11 = i11 + z11 * (h11 - i11);
                S->Ifp[n0 * GP + j1] = I00; S->Ifp[n1 * GP + j1] = I10;
                S->Ifp[n0 * GP + j2] = I01; S->Ifp[n1 * GP + j2] = I11;
                S->st[n0 * SSTR + 64 + j1] = __float2half(I00);
                S->st[n1 * SSTR + 64 + j1] = __float2half(I10);
                S->st[n0 * SSTR + 64 + j2] = __float2half(I01);
                S->st[n1 * SSTR + 64 + j2] = __float2half(I11);
            }
            BARR();  // D: st[I] ready
            // ---- P4: A gate (k over [Wn|In] = bytes 0..255)
            mma_frag<8>(fAg, bb, 0, d);
            S->gtmp[n0 * GP + j1] = sigm_f(d[0] + ba1);
            S->gtmp[n1 * GP + j1] = sigm_f(d[1] + ba1);
            S->gtmp[n0 * GP + j2] = sigm_f(d[2] + ba2);
            S->gtmp[n1 * GP + j2] = sigm_f(d[3] + ba2);
            BARR();  // E
            BARR();  // F
        }
    }
}

extern "C" void kernel_launch(void* const* d_in, const int* in_sizes, int n_in,
                              void* d_out, int out_size) {
    (void)in_sizes; (void)n_in; (void)out_size;
    const size_t shmem = sizeof(Smem);
    cudaFuncSetAttribute(anima_kernel,
                         cudaFuncAttributeMaxDynamicSharedMemorySize,
                         (int)shmem);
    anima_kernel<<<NCTA, NTHREADS, shmem>>>(
        (const float*)d_in[0],
        (const float*)d_in[1], (const float*)d_in[2],
        (const float*)d_in[3], (const float*)d_in[4], (const float*)d_in[5],
        (const float*)d_in[6], (const float*)d_in[7],
        (const float*)d_in[8], (const float*)d_in[9],
        (const float*)d_in[10], (const float*)d_in[11],
        (const float*)d_in[12], (const float*)d_in[13],
        (const float*)d_in[14], (const float*)d_in[15], (const float*)d_in[16],
        (const float*)d_in[17], (const float*)d_in[18],
        (const float*)d_in[19], (const float*)d_in[20],
        (float*)d_out);
}

// round 14
// speedup vs baseline: 5.6170x; 1.0269x over previous
#include <cuda_runtime.h>
#include <cuda_fp16.h>
#include <cstdint>

#define TT 512
#define SDIM 8
#define ODIM 4
#define NTHREADS 256
#define NCTA 128

#define KP3 200   // padded row stride (halves) for 192-k weight blocks
#define KP2 136   // padded row stride for 128-k blocks
#define SSTR 264  // fp16 state row stride (halves): [W:0|I:64|A:128|RI:192]
#define GP  68    // fp32 temp row stride (floats)

struct __align__(16) Smem {
    __half win[64 * KP3];   // [j][ W|I|A ]   (W_from_*)
    __half wz [64 * KP3];   // [j][ Wn|I|A ]  (I_z)
    __half wr [64 * KP3];   // [j][ Wn|I|A ]  (I_r)
    __half wh [64 * KP3];   // [j][ Wn|rI|A ] (I_h)
    __half wa [64 * KP3];   // [j][ Wn|In|A ] (A_from_*)
    __half wg [64 * KP2];   // [j][ I|A ]     (W_gate)
    __half wag[64 * KP2];   // [j][ Wn|In ]   (A_gate)
    __half st [8 * SSTR];   // fp16 states per row: [W | I | A | RI]
    float gtmp[8 * GP];     // Wg sigm early-step; Ag sigm late-step
    float ztmp[8 * GP];     // z
    float Ifp [8 * GP];     // fp32 master of I
    float xs[8][SDIM];
};

extern __shared__ char smem_raw[];

__device__ __forceinline__ float tanh_f(float x) {
    x = fminf(fmaxf(x, -9.0f), 9.0f);
    float e = __expf(2.0f * x);
    return __fdividef(e - 1.0f, e + 1.0f);
}
__device__ __forceinline__ float sigm_f(float x) {
    return __fdividef(1.0f, 1.0f + __expf(-x));
}
__device__ __forceinline__ uint32_t s2u(const void* p) {
    uint32_t a;
    asm("{ .reg .u64 t; cvta.to.shared.u64 t, %1; cvt.u32.u64 %0, t; }"
        : "=r"(a) : "l"(p));
    return a;
}
__device__ __forceinline__ void ldsm4(uint32_t addr, uint32_t& r0, uint32_t& r1,
                                      uint32_t& r2, uint32_t& r3) {
    asm volatile("ldmatrix.sync.aligned.m8n8.x4.shared.b16 {%0,%1,%2,%3}, [%4];"
                 : "=r"(r0), "=r"(r1), "=r"(r2), "=r"(r3) : "r"(addr));
}
__device__ __forceinline__ uint32_t lds32(uint32_t addr) {
    uint32_t v;
    asm volatile("ld.shared.b32 %0, [%1];" : "=r"(v) : "r"(addr));
    return v;
}
__device__ __forceinline__ void mma16816(float& d0, float& d1, float& d2, float& d3,
                                         uint32_t a0, uint32_t a1, uint32_t a2,
                                         uint32_t a3, uint32_t b0, uint32_t b1) {
    asm volatile(
        "mma.sync.aligned.m16n8k16.row.col.f32.f16.f16.f32 "
        "{%0,%1,%2,%3}, {%4,%5,%6,%7}, {%8,%9}, {%0,%1,%2,%3};"
        : "+f"(d0), "+f"(d1), "+f"(d2), "+f"(d3)
        : "r"(a0), "r"(a1), "r"(a2), "r"(a3), "r"(b0), "r"(b1));
}

#define BSYNC(id, n)   asm volatile("bar.sync %0, %1;"   :: "r"(id), "r"(n) : "memory")
#define BARRIVE(id, n) asm volatile("bar.arrive %0, %1;" :: "r"(id), "r"(n) : "memory")

// accumulate N k-tiles into (d,e) accumulator pair; B offsets bstart + i*32 bytes
template <int N>
__device__ __forceinline__ void mma_acc(const uint32_t (*f)[4], uint32_t bb,
                                        int bstart, float (&d)[4], float (&e)[4]) {
#pragma unroll
    for (int i = 0; i < N; i++) {
        uint32_t b0 = lds32(bb + bstart + i * 32);
        uint32_t b1 = lds32(bb + bstart + i * 32 + 16);
        float* a = (i & 1) ? e : d;
        mma16816(a[0], a[1], a[2], a[3],
                 f[i][0], f[i][1], f[i][2], f[i][3], b0, b1);
    }
}

__device__ __forceinline__ void stage_mat(__half* dst, int Kp, int koff,
                                          const float* __restrict__ src, int K) {
#pragma unroll 1
    for (int i = threadIdx.x; i < K * 64; i += NTHREADS) {
        int k = i >> 6, j = i & 63;
        dst[j * Kp + koff + k] = __float2half(src[i]);
    }
}

// Barrier ids:
//  b1: Wg ready        (half1 arrive, half0 sync, 256)
//  b3: W_new ready     (half0 arrive, half1 sync, 256)
//  b4: z ready         (half0 arrive, half1 sync, 256)
//  b6: I_new ready     (half1 arrive, half0 sync, 256)
//  b8: Ag ready        (half1 arrive, half0 sync, 256)
//  b9: A_new ready     (half0 arrive, half1 sync, 256)
//  b2: half0 internal (128)  [after W store; after A store]
//  b5: half1 internal (128)  [RI ready]
//  b7: half1 internal (128)  [I store before Ag In-part]

__global__ void __launch_bounds__(NTHREADS, 1)
anima_kernel(const float* __restrict__ x,
             const float* __restrict__ we_w, const float* __restrict__ we_b,
             const float* __restrict__ WfW, const float* __restrict__ WfI,
             const float* __restrict__ WfA,
             const float* __restrict__ Wg_w, const float* __restrict__ Wg_b,
             const float* __restrict__ Iz_w, const float* __restrict__ Iz_b,
             const float* __restrict__ Ir_w, const float* __restrict__ Ir_b,
             const float* __restrict__ Ih_w, const float* __restrict__ Ih_b,
             const float* __restrict__ AfW, const float* __restrict__ AfI,
             const float* __restrict__ AfA,
             const float* __restrict__ Ag_w, const float* __restrict__ Ag_b,
             const float* __restrict__ phi_w, const float* __restrict__ phi_b,
             float* __restrict__ out) {
    Smem* S = reinterpret_cast<Smem*>(smem_raw);
    const int tid = threadIdx.x;

    // ---- one-time staging (transposed, k-concatenated)
    stage_mat(S->win, KP3, 0, WfW, 64);
    stage_mat(S->win, KP3, 64, WfI, 64);
    stage_mat(S->win, KP3, 128, WfA, 64);
    stage_mat(S->wz, KP3, 0, Iz_w, 192);
    stage_mat(S->wr, KP3, 0, Ir_w, 192);
    stage_mat(S->wh, KP3, 0, Ih_w, 192);
    stage_mat(S->wa, KP3, 0, AfW, 64);
    stage_mat(S->wa, KP3, 64, AfI, 64);
    stage_mat(S->wa, KP3, 128, AfA, 64);
    stage_mat(S->wg, KP2, 0, Wg_w, 128);
    stage_mat(S->wag, KP2, 0, Ag_w, 128);

#pragma unroll 1
    for (int i = tid; i < 8 * SSTR / 2; i += NTHREADS)
        reinterpret_cast<uint32_t*>(S->st)[i] = 0u;
#pragma unroll 1
    for (int i = tid; i < 8 * GP; i += NTHREADS) S->Ifp[i] = 0.f;

    // ---- common mapping
    const int lane = tid & 31, w = tid >> 5;
    const int jt = w & 3;
    const int g = lane >> 2, t4 = lane & 3;
    const int rl = (lane & 7) | (((lane >> 3) & 1) << 3);
    const int c8 = (lane >> 4) * 8;
    const int j1 = jt * 16 + g, j2 = j1 + 8;
    const int n0 = 2 * t4, n1 = n0 + 1;
    const long base = (long)blockIdx.x * 8;
    const uint32_t arow3 = ((jt * 16 + rl) * KP3 + c8) * 2;
    const uint32_t arow2 = ((jt * 16 + rl) * KP2 + c8) * 2;
    const uint32_t bb = s2u(S->st) + g * (SSTR * 2) + t4 * 4;

    // stage x(0)
    const int xrow = tid >> 3, xc = tid & 7;
    const float* xptr = x + (base + xrow) * (TT * SDIM) + xc;
    if (tid < 64) S->xs[xrow][xc] = xptr[0];
    __syncthreads();

    if (w < 4) {
        // ============ half0: W_in, z, A_in, encoder, A_new, P5, x ============
        uint32_t fW[12][4], fZ[12][4], fA[12][4];
        {
            const uint32_t aW_ = s2u(S->win) + arow3;
            const uint32_t aZ_ = s2u(S->wz) + arow3;
            const uint32_t aA_ = s2u(S->wa) + arow3;
#pragma unroll
            for (int kt = 0; kt < 12; kt++)
                ldsm4(aW_ + kt * 32, fW[kt][0], fW[kt][1], fW[kt][2], fW[kt][3]);
#pragma unroll
            for (int kt = 0; kt < 12; kt++)
                ldsm4(aZ_ + kt * 32, fZ[kt][0], fZ[kt][1], fZ[kt][2], fZ[kt][3]);
#pragma unroll
            for (int kt = 0; kt < 12; kt++)
                ldsm4(aA_ + kt * 32, fA[kt][0], fA[kt][1], fA[kt][2], fA[kt][3]);
        }
        float we1[8], we2[8];
#pragma unroll
        for (int s = 0; s < 8; s++) {
            we1[s] = we_w[s * 64 + j1];
            we2[s] = we_w[s * 64 + j2];
        }
        const float be1 = we_b[j1], be2 = we_b[j2];
        const float bz1 = Iz_b[j1], bz2 = Iz_b[j2];
        const int o5 = lane & 3, sg = (lane >> 2) & 3, rsel = lane >> 4;
        const int prow = w * 2 + rsel;
        float ph[16];
#pragma unroll
        for (int kk = 0; kk < 16; kk++) ph[kk] = phi_w[(sg * 16 + kk) * 4 + o5];
        const float bphi = phi_b[o5];
        float xv = (tid < 64) ? xptr[SDIM] : 0.f;

        for (int t_ = 0; t_ < TT; t_++) {
            // -- precompute (no waits): W_in full; z over [I|A]; A_in over [A]
            float dW[4] = {}, eW[4] = {};
            mma_acc<12>(&fW[0], bb, 0, dW, eW);
            float zd[4] = {}, ze[4] = {};
            mma_acc<8>(&fZ[4], bb, 128, zd, ze);
            float ad[4] = {}, ae[4] = {};
            mma_acc<4>(&fA[8], bb, 256, ad, ae);

            BSYNC(1, 256);  // Wg ready
            {   // W epilogue: encoder + tanh * gate ; store st[W]
                const float* x0 = S->xs[n0];
                const float* x1 = S->xs[n1];
                float e00 = be1, e10 = be1, e01 = be2, e11 = be2;
#pragma unroll
                for (int s = 0; s < 8; s++) {
                    e00 = fmaf(x0[s], we1[s], e00);
                    e10 = fmaf(x1[s], we1[s], e10);
                    e01 = fmaf(x0[s], we2[s], e01);
                    e11 = fmaf(x1[s], we2[s], e11);
                }
                float w00 = tanh_f(dW[0] + eW[0] + tanh_f(e00)) * S->gtmp[n0 * GP + j1];
                float w10 = tanh_f(dW[1] + eW[1] + tanh_f(e10)) * S->gtmp[n1 * GP + j1];
                float w01 = tanh_f(dW[2] + eW[2] + tanh_f(e01)) * S->gtmp[n0 * GP + j2];
                float w11 = tanh_f(dW[3] + eW[3] + tanh_f(e11)) * S->gtmp[n1 * GP + j2];
                S->st[n0 * SSTR + j1] = __float2half(w00);
                S->st[n1 * SSTR + j1] = __float2half(w10);
                S->st[n0 * SSTR + j2] = __float2half(w01);
                S->st[n1 * SSTR + j2] = __float2half(w11);
            }
            BARRIVE(3, 256);  // -> half1: W ready
            BSYNC(2, 128);    // half0 internal: all W stores visible

            // -- z dependent part (4 tiles on W) + store
            mma_acc<4>(&fZ[0], bb, 0, zd, ze);
            S->ztmp[n0 * GP + j1] = sigm_f(zd[0] + ze[0] + bz1);
            S->ztmp[n1 * GP + j1] = sigm_f(zd[1] + ze[1] + bz1);
            S->ztmp[n0 * GP + j2] = sigm_f(zd[2] + ze[2] + bz2);
            S->ztmp[n1 * GP + j2] = sigm_f(zd[3] + ze[3] + bz2);
            BARRIVE(4, 256);  // -> half1: z ready

            // -- A_in Wn part (precomputable w.r.t. I)
            mma_acc<4>(&fA[0], bb, 0, ad, ae);
            BSYNC(6, 256);    // wait I_new
            mma_acc<4>(&fA[4], bb, 128, ad, ae);
            BSYNC(8, 256);    // wait Ag
            {
                float a00 = tanh_f(ad[0] + ae[0]) * S->gtmp[n0 * GP + j1];
                float a10 = tanh_f(ad[1] + ae[1]) * S->gtmp[n1 * GP + j1];
                float a01 = tanh_f(ad[2] + ae[2]) * S->gtmp[n0 * GP + j2];
                float a11 = tanh_f(ad[3] + ae[3]) * S->gtmp[n1 * GP + j2];
                S->st[n0 * SSTR + 128 + j1] = __float2half(a00);
                S->st[n1 * SSTR + 128 + j1] = __float2half(a10);
                S->st[n0 * SSTR + 128 + j2] = __float2half(a01);
                S->st[n1 * SSTR + 128 + j2] = __float2half(a11);
            }
            if (tid < 64) {
                S->xs[xrow][xc] = xv;  // x(t+1)
                if (t_ + 2 < TT) xv = xptr[(t_ + 2) * SDIM];
            }
            BARRIVE(9, 256);  // -> half1: A ready
            BSYNC(2, 128);    // half0 internal: A stores + xs visible

            // -- P5: action(t) = A_new @ phi + b (overlaps half1's Wg(t+1))
            {
                const __half* ap = S->st + prow * SSTR + 128 + sg * 16;
                uint4 v0 = *reinterpret_cast<const uint4*>(ap);
                uint4 v1 = *reinterpret_cast<const uint4*>(ap + 8);
                const __half2* h0 = reinterpret_cast<const __half2*>(&v0);
                const __half2* h1 = reinterpret_cast<const __half2*>(&v1);
                float p = 0.f;
#pragma unroll
                for (int q = 0; q < 4; q++) {
                    float2 f0 = __half22float2(h0[q]);
                    float2 f1 = __half22float2(h1[q]);
                    p = fmaf(f0.x, ph[2 * q], p);
                    p = fmaf(f0.y, ph[2 * q + 1], p);
                    p = fmaf(f1.x, ph[8 + 2 * q], p);
                    p = fmaf(f1.y, ph[9 + 2 * q], p);
                }
                p += __shfl_xor_sync(0xffffffffu, p, 4);
                p += __shfl_xor_sync(0xffffffffu, p, 8);
                if (sg == 0)
                    out[(base + prow) * (TT * ODIM) + t_ * ODIM + o5] = p + bphi;
            }
        }
    } else {
        // ============ half1: Wg, r->RI, h->I_new, Ag ============
        uint32_t fG[8][4], fR[12][4], fH[12][4], fAg[8][4];
        {
            const uint32_t aG_ = s2u(S->wg) + arow2;
            const uint32_t aR_ = s2u(S->wr) + arow3;
            const uint32_t aH_ = s2u(S->wh) + arow3;
            const uint32_t aAg_ = s2u(S->wag) + arow2;
#pragma unroll
            for (int kt = 0; kt < 8; kt++)
                ldsm4(aG_ + kt * 32, fG[kt][0], fG[kt][1], fG[kt][2], fG[kt][3]);
#pragma unroll
            for (int kt = 0; kt < 12; kt++)
                ldsm4(aR_ + kt * 32, fR[kt][0], fR[kt][1], fR[kt][2], fR[kt][3]);
#pragma unroll
            for (int kt = 0; kt < 12; kt++)
                ldsm4(aH_ + kt * 32, fH[kt][0], fH[kt][1], fH[kt][2], fH[kt][3]);
#pragma unroll
            for (int kt = 0; kt < 8; kt++)
                ldsm4(aAg_ + kt * 32, fAg[kt][0], fAg[kt][1], fAg[kt][2], fAg[kt][3]);
        }
        const float bg1 = Wg_b[j1], bg2 = Wg_b[j2];
        const float br1 = Ir_b[j1], br2 = Ir_b[j2];
        const float bh1 = Ih_b[j1], bh2 = Ih_b[j2];
        const float ba1 = Ag_b[j1], ba2 = Ag_b[j2];

        for (int t_ = 0; t_ < TT; t_++) {
            // -- Wg: fully precomputable (k over [I|A])
            {
                float d[4] = {}, e[4] = {};
                mma_acc<8>(&fG[0], bb, 128, d, e);
                S->gtmp[n0 * GP + j1] = sigm_f(d[0] + e[0] + bg1);
                S->gtmp[n1 * GP + j1] = sigm_f(d[1] + e[1] + bg1);
                S->gtmp[n0 * GP + j2] = sigm_f(d[2] + e[2] + bg2);
                S->gtmp[n1 * GP + j2] = sigm_f(d[3] + e[3] + bg2);
            }
            BARRIVE(1, 256);  // -> half0: Wg ready

            // -- precompute: r over [I|A]; h over [A]
            float rd[4] = {}, re[4] = {};
            mma_acc<8>(&fR[4], bb, 128, rd, re);
            float hd[4] = {}, he[4] = {};
            mma_acc<4>(&fH[8], bb, 256, hd, he);

            BSYNC(3, 256);    // W ready
            // -- r dependent part -> RI
            mma_acc<4>(&fR[0], bb, 0, rd, re);
            {
                float r00 = sigm_f(rd[0] + re[0] + br1);
                float r10 = sigm_f(rd[1] + re[1] + br1);
                float r01 = sigm_f(rd[2] + re[2] + br2);
                float r11 = sigm_f(rd[3] + re[3] + br2);
                S->st[n0 * SSTR + 192 + j1] =
                    __float2half(r00 * S->Ifp[n0 * GP + j1]);
                S->st[n1 * SSTR + 192 + j1] =
                    __float2half(r10 * S->Ifp[n1 * GP + j1]);
                S->st[n0 * SSTR + 192 + j2] =
                    __float2half(r01 * S->Ifp[n0 * GP + j2]);
                S->st[n1 * SSTR + 192 + j2] =
                    __float2half(r11 * S->Ifp[n1 * GP + j2]);
            }
            BSYNC(5, 128);    // half1 internal: RI visible

            // -- h dependent parts: Wn (bytes 0) + RI (bytes 384)
            mma_acc<4>(&fH[0], bb, 0, hd, he);
            mma_acc<4>(&fH[4], bb, 384, hd, he);
            BSYNC(4, 256);    // z ready
            {   // I epilogue
                float h00 = tanh_f(hd[0] + he[0] + bh1);
                float h10 = tanh_f(hd[1] + he[1] + bh1);
                float h01 = tanh_f(hd[2] + he[2] + bh2);
                float h11 = tanh_f(hd[3] + he[3] + bh2);
                float z00 = S->ztmp[n0 * GP + j1], z10 = S->ztmp[n1 * GP + j1];
                float z01 = S->ztmp[n0 * GP + j2], z11 = S->ztmp[n1 * GP + j2];
                float i00 = S->Ifp[n0 * GP + j1], i10 = S->Ifp[n1 * GP + j1];
                float i01 = S->Ifp[n0 * GP + j2], i11 = S->Ifp[n1 * GP + j2];
                float I00 = i00 + z00 * (h00 - i00);
                float I10 = i10 + z10 * (h10 - i10);
                float I01 = i01 + z01 * (h01 - i01);
                float I11 = i11 + z11 * (h11 - i11);
                S->Ifp[n0 * GP + j1] = I00; S->Ifp[n1 * GP + j1] = I10;
                S->Ifp[n0 * GP + j2] = I01; S->Ifp[n1 * GP + j2] = I11;
                S->st[n0 * SSTR + 64 + j1] = __float2half(I00);
                S->st[n1 * SSTR + 64 + j1] = __float2half(I10);
                S->st[n0 * SSTR + 64 + j2] = __float2half(I01);
                S->st[n1 * SSTR + 64 + j2] = __float2half(I11);
            }
            BARRIVE(6, 256);  // -> half0: I ready
            BSYNC(7, 128);    // half1 internal: I stores visible

            // -- Ag over [Wn|In]
            {
                float d[4] = {}, e[4] = {};
                mma_acc<8>(&fAg[0], bb, 0, d, e);
                S->gtmp[n0 * GP + j1] = sigm_f(d[0] + e[0] + ba1);
                S->gtmp[n1 * GP + j1] = sigm_f(d[1] + e[1] + ba1);
                S->gtmp[n0 * GP + j2] = sigm_f(d[2] + e[2] + ba2);
                S->gtmp[n1 * GP + j2] = sigm_f(d[3] + e[3] + ba2);
            }
            BARRIVE(8, 256);  // -> half0: Ag ready
            BSYNC(9, 256);    // A ready (for next step's precomputes)
        }
    }
}

extern "C" void kernel_launch(void* const* d_in, const int* in_sizes, int n_in,
                              void* d_out, int out_size) {
    (void)in_sizes; (void)n_in; (void)out_size;
    const size_t shmem = sizeof(Smem);
    cudaFuncSetAttribute(anima_kernel,
                         cudaFuncAttributeMaxDynamicSharedMemorySize,
                         (int)shmem);
    anima_kernel<<<NCTA, NTHREADS, shmem>>>(
        (const float*)d_in[0],
        (const float*)d_in[1], (const float*)d_in[2],
        (const float*)d_in[3], (const float*)d_in[4], (const float*)d_in[5],
        (const float*)d_in[6], (const float*)d_in[7],
        (const float*)d_in[8], (const float*)d_in[9],
        (const float*)d_in[10], (const float*)d_in[11],
        (const float*)d_in[12], (const float*)d_in[13],
        (const float*)d_in[14], (const float*)d_in[15], (const float*)d_in[16],
        (const float*)d_in[17], (const float*)d_in[18],
        (const float*)d_in[19], (const float*)d_in[20],
        (float*)d_out);
}

// round 15
// speedup vs baseline: 6.0128x; 1.0705x over previous
#include <cuda_runtime.h>
#include <cuda_fp16.h>
#include <cstdint>

#define TT 512
#define SDIM 8
#define ODIM 4
#define NTHREADS 256
#define NCTA 128

#define KP3 200   // padded row stride (halves) for 192-k weight blocks
#define KP2 136   // padded row stride for 128-k blocks
#define SSTR 264  // fp16 state row stride (halves): [W:0|I:64|A:128|RI:192]
#define GP  68    // fp32 temp row stride (floats)

struct __align__(16) Smem {
    __half win[64 * KP3];   // [j][ W|I|A ]   (W_from_*)
    __half wz [64 * KP3];   // [j][ Wn|I|A ]  (I_z)
    __half wr [64 * KP3];   // [j][ Wn|I|A ]  (I_r)
    __half wh [64 * KP3];   // [j][ Wn|rI|A ] (I_h)
    __half wa [64 * KP3];   // [j][ Wn|In|A ] (A_from_*)
    __half wg [64 * KP2];   // [j][ I|A ]     (W_gate)
    __half wag[64 * KP2];   // [j][ Wn|In ]   (A_gate)
    __half st [8 * SSTR];   // fp16 states per row: [W@0B | I@128B | A@256B | RI@384B]
    float gtmp[8 * GP];     // Wg sigm early-step; Ag sigm late-step
    float ztmp[8 * GP];     // z
    float Ifp [8 * GP];     // fp32 master of I
    float xs[8][SDIM];
};

extern __shared__ char smem_raw[];

__device__ __forceinline__ float tanh_f(float x) {
    x = fminf(fmaxf(x, -9.0f), 9.0f);
    float e = __expf(2.0f * x);
    return __fdividef(e - 1.0f, e + 1.0f);
}
__device__ __forceinline__ float sigm_f(float x) {
    return __fdividef(1.0f, 1.0f + __expf(-x));
}
__device__ __forceinline__ uint32_t s2u(const void* p) {
    uint32_t a;
    asm("{ .reg .u64 t; cvta.to.shared.u64 t, %1; cvt.u32.u64 %0, t; }"
        : "=r"(a) : "l"(p));
    return a;
}
__device__ __forceinline__ void ldsm4(uint32_t addr, uint32_t& r0, uint32_t& r1,
                                      uint32_t& r2, uint32_t& r3) {
    asm volatile("ldmatrix.sync.aligned.m8n8.x4.shared.b16 {%0,%1,%2,%3}, [%4];"
                 : "=r"(r0), "=r"(r1), "=r"(r2), "=r"(r3) : "r"(addr));
}
__device__ __forceinline__ uint32_t lds32(uint32_t addr) {
    uint32_t v;
    asm volatile("ld.shared.b32 %0, [%1];" : "=r"(v) : "r"(addr));
    return v;
}
__device__ __forceinline__ void mma16816(float& d0, float& d1, float& d2, float& d3,
                                         uint32_t a0, uint32_t a1, uint32_t a2,
                                         uint32_t a3, uint32_t b0, uint32_t b1) {
    asm volatile(
        "mma.sync.aligned.m16n8k16.row.col.f32.f16.f16.f32 "
        "{%0,%1,%2,%3}, {%4,%5,%6,%7}, {%8,%9}, {%0,%1,%2,%3};"
        : "+f"(d0), "+f"(d1), "+f"(d2), "+f"(d3)
        : "r"(a0), "r"(a1), "r"(a2), "r"(a3), "r"(b0), "r"(b1));
}

#define BSYNC(id, n)   asm volatile("bar.sync %0, %1;"   :: "r"(id), "r"(n) : "memory")
#define BARRIVE(id, n) asm volatile("bar.arrive %0, %1;" :: "r"(id), "r"(n) : "memory")

// accumulate N k-tiles into (d,e) accumulator pair; B offsets bstart + i*32 bytes
template <int N>
__device__ __forceinline__ void mma_acc(const uint32_t (*f)[4], uint32_t bb,
                                        int bstart, float (&d)[4], float (&e)[4]) {
#pragma unroll
    for (int i = 0; i < N; i++) {
        uint32_t b0 = lds32(bb + bstart + i * 32);
        uint32_t b1 = lds32(bb + bstart + i * 32 + 16);
        float* a = (i & 1) ? e : d;
        mma16816(a[0], a[1], a[2], a[3],
                 f[i][0], f[i][1], f[i][2], f[i][3], b0, b1);
    }
}

__device__ __forceinline__ void stage_mat(__half* dst, int Kp, int koff,
                                          const float* __restrict__ src, int K) {
#pragma unroll 1
    for (int i = threadIdx.x; i < K * 64; i += NTHREADS) {
        int k = i >> 6, j = i & 63;
        dst[j * Kp + koff + k] = __float2half(src[i]);
    }
}

// Barriers (counts: 256 unless noted):
//  b1: Wg ready     (h1 arrive, h0 sync)
//  b3: W_new ready  (h0 arrive, h1 sync)
//  b4: z ready      (h0 arrive, h1 sync)
//  b6: I_new ready  (h1 arrive, h0 sync)
//  b8: Ag ready     (h1 arrive, h0 sync)
//  b9: A_new ready  (h0 arrive, h1 sync)
//  b2: half0 internal (128, twice per step)
//  b5, b7: half1 internal (128)

__global__ void __launch_bounds__(NTHREADS, 1)
anima_kernel(const float* __restrict__ x,
             const float* __restrict__ we_w, const float* __restrict__ we_b,
             const float* __restrict__ WfW, const float* __restrict__ WfI,
             const float* __restrict__ WfA,
             const float* __restrict__ Wg_w, const float* __restrict__ Wg_b,
             const float* __restrict__ Iz_w, const float* __restrict__ Iz_b,
             const float* __restrict__ Ir_w, const float* __restrict__ Ir_b,
             const float* __restrict__ Ih_w, const float* __restrict__ Ih_b,
             const float* __restrict__ AfW, const float* __restrict__ AfI,
             const float* __restrict__ AfA,
             const float* __restrict__ Ag_w, const float* __restrict__ Ag_b,
             const float* __restrict__ phi_w, const float* __restrict__ phi_b,
             float* __restrict__ out) {
    Smem* S = reinterpret_cast<Smem*>(smem_raw);
    const int tid = threadIdx.x;

    // ---- one-time staging (transposed, k-concatenated)
    stage_mat(S->win, KP3, 0, WfW, 64);
    stage_mat(S->win, KP3, 64, WfI, 64);
    stage_mat(S->win, KP3, 128, WfA, 64);
    stage_mat(S->wz, KP3, 0, Iz_w, 192);
    stage_mat(S->wr, KP3, 0, Ir_w, 192);
    stage_mat(S->wh, KP3, 0, Ih_w, 192);
    stage_mat(S->wa, KP3, 0, AfW, 64);
    stage_mat(S->wa, KP3, 64, AfI, 64);
    stage_mat(S->wa, KP3, 128, AfA, 64);
    stage_mat(S->wg, KP2, 0, Wg_w, 128);
    stage_mat(S->wag, KP2, 0, Ag_w, 128);

#pragma unroll 1
    for (int i = tid; i < 8 * SSTR / 2; i += NTHREADS)
        reinterpret_cast<uint32_t*>(S->st)[i] = 0u;
#pragma unroll 1
    for (int i = tid; i < 8 * GP; i += NTHREADS) S->Ifp[i] = 0.f;

    // ---- common mapping
    const int lane = tid & 31, w = tid >> 5;
    const int jt = w & 3;
    const int g = lane >> 2, t4 = lane & 3;
    const int rl = (lane & 7) | (((lane >> 3) & 1) << 3);
    const int c8 = (lane >> 4) * 8;
    const int j1 = jt * 16 + g, j2 = j1 + 8;
    const int n0 = 2 * t4, n1 = n0 + 1;
    const long base = (long)blockIdx.x * 8;
    const uint32_t arow3 = ((jt * 16 + rl) * KP3 + c8) * 2;
    const uint32_t arow2 = ((jt * 16 + rl) * KP2 + c8) * 2;
    const uint32_t bb = s2u(S->st) + g * (SSTR * 2) + t4 * 4;

    // stage x(0)
    const int xrow = tid >> 3, xc = tid & 7;
    const float* xptr = x + (base + xrow) * (TT * SDIM) + xc;
    if (tid < 64) S->xs[xrow][xc] = xptr[0];
    __syncthreads();

    if (w < 4) {
        // ============ half0: W_in, z, A_in, W/A epilogues, P5, x ============
        uint32_t fW[12][4], fZ[12][4], fA[12][4];
        {
            const uint32_t aW_ = s2u(S->win) + arow3;
            const uint32_t aZ_ = s2u(S->wz) + arow3;
            const uint32_t aA_ = s2u(S->wa) + arow3;
#pragma unroll
            for (int kt = 0; kt < 12; kt++)
                ldsm4(aW_ + kt * 32, fW[kt][0], fW[kt][1], fW[kt][2], fW[kt][3]);
#pragma unroll
            for (int kt = 0; kt < 12; kt++)
                ldsm4(aZ_ + kt * 32, fZ[kt][0], fZ[kt][1], fZ[kt][2], fZ[kt][3]);
#pragma unroll
            for (int kt = 0; kt < 12; kt++)
                ldsm4(aA_ + kt * 32, fA[kt][0], fA[kt][1], fA[kt][2], fA[kt][3]);
        }
        float we1[8], we2[8];
#pragma unroll
        for (int s = 0; s < 8; s++) {
            we1[s] = we_w[s * 64 + j1];
            we2[s] = we_w[s * 64 + j2];
        }
        const float be1 = we_b[j1], be2 = we_b[j2];
        const float bz1 = Iz_b[j1], bz2 = Iz_b[j2];
        const int o5 = lane & 3, sg = (lane >> 2) & 3, rsel = lane >> 4;
        const int prow = w * 2 + rsel;
        float ph[16];
#pragma unroll
        for (int kk = 0; kk < 16; kk++) ph[kk] = phi_w[(sg * 16 + kk) * 4 + o5];
        const float bphi = phi_b[o5];
        float xv = (tid < 64) ? xptr[SDIM] : 0.f;

        // carried partials (zero at t=0: states are zero) + enc(0)
        float cW[4] = {}, cWe[4] = {}, cZ[4] = {}, cZe[4] = {};
        float enc[4];
        {
            const float* x0 = S->xs[n0];
            const float* x1 = S->xs[n1];
            float e00 = be1, e10 = be1, e01 = be2, e11 = be2;
#pragma unroll
            for (int s = 0; s < 8; s++) {
                e00 = fmaf(x0[s], we1[s], e00);
                e10 = fmaf(x1[s], we1[s], e10);
                e01 = fmaf(x0[s], we2[s], e01);
                e11 = fmaf(x1[s], we2[s], e11);
            }
            enc[0] = tanh_f(e00); enc[1] = tanh_f(e10);
            enc[2] = tanh_f(e01); enc[3] = tanh_f(e11);
        }

        for (int t_ = 0; t_ < TT; t_++) {
            // -- step top: A(t-1)-dependent parts only
            mma_acc<4>(&fW[8], bb, 256, cW, cWe);   // W_in A-part
            float aA[4] = {}, aAe[4] = {};
            mma_acc<4>(&fA[8], bb, 256, aA, aAe);   // A_in A-part
            mma_acc<4>(&fZ[8], bb, 256, cZ, cZe);   // z A-part

            BSYNC(1, 256);  // Wg ready
            {   // W epilogue (enc pre-tanh'd in shadow)
                float w00 = tanh_f(cW[0] + cWe[0] + enc[0]) * S->gtmp[n0 * GP + j1];
                float w10 = tanh_f(cW[1] + cWe[1] + enc[1]) * S->gtmp[n1 * GP + j1];
                float w01 = tanh_f(cW[2] + cWe[2] + enc[2]) * S->gtmp[n0 * GP + j2];
                float w11 = tanh_f(cW[3] + cWe[3] + enc[3]) * S->gtmp[n1 * GP + j2];
                S->st[n0 * SSTR + j1] = __float2half(w00);
                S->st[n1 * SSTR + j1] = __float2half(w10);
                S->st[n0 * SSTR + j2] = __float2half(w01);
                S->st[n1 * SSTR + j2] = __float2half(w11);
            }
            BARRIVE(3, 256);  // -> half1: W ready
            BSYNC(2, 128);    // half0 internal: W stores visible

            // -- z W-part + store
            mma_acc<4>(&fZ[0], bb, 0, cZ, cZe);
            S->ztmp[n0 * GP + j1] = sigm_f(cZ[0] + cZe[0] + bz1);
            S->ztmp[n1 * GP + j1] = sigm_f(cZ[1] + cZe[1] + bz1);
            S->ztmp[n0 * GP + j2] = sigm_f(cZ[2] + cZe[2] + bz2);
            S->ztmp[n1 * GP + j2] = sigm_f(cZ[3] + cZe[3] + bz2);
            BARRIVE(4, 256);  // -> half1: z ready

            // -- A_in W-part (shadow w.r.t. I)
            mma_acc<4>(&fA[0], bb, 0, aA, aAe);
            BSYNC(6, 256);    // I_new ready
            mma_acc<4>(&fA[4], bb, 128, aA, aAe);   // A_in I-part
            BSYNC(8, 256);    // Ag ready
            {   // A epilogue
                float a00 = tanh_f(aA[0] + aAe[0]) * S->gtmp[n0 * GP + j1];
                float a10 = tanh_f(aA[1] + aAe[1]) * S->gtmp[n1 * GP + j1];
                float a01 = tanh_f(aA[2] + aAe[2]) * S->gtmp[n0 * GP + j2];
                float a11 = tanh_f(aA[3] + aAe[3]) * S->gtmp[n1 * GP + j2];
                S->st[n0 * SSTR + 128 + j1] = __float2half(a00);
                S->st[n1 * SSTR + 128 + j1] = __float2half(a10);
                S->st[n0 * SSTR + 128 + j2] = __float2half(a01);
                S->st[n1 * SSTR + 128 + j2] = __float2half(a11);
            }
            if (tid < 64) {
                S->xs[xrow][xc] = xv;  // x(t+1)
                if (t_ + 2 < TT) xv = xptr[(t_ + 2) * SDIM];
            }
            BARRIVE(9, 256);  // -> half1: A ready
            BSYNC(2, 128);    // half0 internal: A stores + xs visible

            // ---- shadow for t+1: W_in [W|I], z [I], enc, P5 ----
#pragma unroll
            for (int i = 0; i < 4; i++) { cW[i] = 0.f; cWe[i] = 0.f;
                                          cZ[i] = 0.f; cZe[i] = 0.f; }
            mma_acc<4>(&fW[0], bb, 0, cW, cWe);     // W-part (W1)
            mma_acc<4>(&fW[4], bb, 128, cW, cWe);   // I-part (I1)
            mma_acc<4>(&fZ[4], bb, 128, cZ, cZe);   // z I-part (I1)
            {
                const float* x0 = S->xs[n0];
                const float* x1 = S->xs[n1];
                float e00 = be1, e10 = be1, e01 = be2, e11 = be2;
#pragma unroll
                for (int s = 0; s < 8; s++) {
                    e00 = fmaf(x0[s], we1[s], e00);
                    e10 = fmaf(x1[s], we1[s], e10);
                    e01 = fmaf(x0[s], we2[s], e01);
                    e11 = fmaf(x1[s], we2[s], e11);
                }
                enc[0] = tanh_f(e00); enc[1] = tanh_f(e10);
                enc[2] = tanh_f(e01); enc[3] = tanh_f(e11);
            }
            {   // P5: action(t) = A_new @ phi + b
                const __half* ap = S->st + prow * SSTR + 128 + sg * 16;
                uint4 v0 = *reinterpret_cast<const uint4*>(ap);
                uint4 v1 = *reinterpret_cast<const uint4*>(ap + 8);
                const __half2* h0 = reinterpret_cast<const __half2*>(&v0);
                const __half2* h1 = reinterpret_cast<const __half2*>(&v1);
                float p = 0.f;
#pragma unroll
                for (int q = 0; q < 4; q++) {
                    float2 f0 = __half22float2(h0[q]);
                    float2 f1 = __half22float2(h1[q]);
                    p = fmaf(f0.x, ph[2 * q], p);
                    p = fmaf(f0.y, ph[2 * q + 1], p);
                    p = fmaf(f1.x, ph[8 + 2 * q], p);
                    p = fmaf(f1.y, ph[9 + 2 * q], p);
                }
                p += __shfl_xor_sync(0xffffffffu, p, 4);
                p += __shfl_xor_sync(0xffffffffu, p, 8);
                if (sg == 0)
                    out[(base + prow) * (TT * ODIM) + t_ * ODIM + o5] = p + bphi;
            }
        }
    } else {
        // ============ half1: Wg, r->RI, h->I_new, Ag ============
        uint32_t fG[8][4], fR[12][4], fH[12][4], fAg[8][4];
        {
            const uint32_t aG_ = s2u(S->wg) + arow2;
            const uint32_t aR_ = s2u(S->wr) + arow3;
            const uint32_t aH_ = s2u(S->wh) + arow3;
            const uint32_t aAg_ = s2u(S->wag) + arow2;
#pragma unroll
            for (int kt = 0; kt < 8; kt++)
                ldsm4(aG_ + kt * 32, fG[kt][0], fG[kt][1], fG[kt][2], fG[kt][3]);
#pragma unroll
            for (int kt = 0; kt < 12; kt++)
                ldsm4(aR_ + kt * 32, fR[kt][0], fR[kt][1], fR[kt][2], fR[kt][3]);
#pragma unroll
            for (int kt = 0; kt < 12; kt++)
                ldsm4(aH_ + kt * 32, fH[kt][0], fH[kt][1], fH[kt][2], fH[kt][3]);
#pragma unroll
            for (int kt = 0; kt < 8; kt++)
                ldsm4(aAg_ + kt * 32, fAg[kt][0], fAg[kt][1], fAg[kt][2], fAg[kt][3]);
        }
        const float bg1 = Wg_b[j1], bg2 = Wg_b[j2];
        const float br1 = Ir_b[j1], br2 = Ir_b[j2];
        const float bh1 = Ih_b[j1], bh2 = Ih_b[j2];
        const float ba1 = Ag_b[j1], ba2 = Ag_b[j2];

        // carried partials (zero at t=0)
        float cG[4] = {}, cGe[4] = {}, cR[4] = {}, cRe[4] = {};

        for (int t_ = 0; t_ < TT; t_++) {
            // -- step top: Wg A-part, then store gate
            mma_acc<4>(&fG[4], bb, 256, cG, cGe);
            S->gtmp[n0 * GP + j1] = sigm_f(cG[0] + cGe[0] + bg1);
            S->gtmp[n1 * GP + j1] = sigm_f(cG[1] + cGe[1] + bg1);
            S->gtmp[n0 * GP + j2] = sigm_f(cG[2] + cGe[2] + bg2);
            S->gtmp[n1 * GP + j2] = sigm_f(cG[3] + cGe[3] + bg2);
            BARRIVE(1, 256);  // -> half0: Wg ready

            // -- A-dependent precomputes (off critical path)
            mma_acc<4>(&fR[8], bb, 256, cR, cRe);   // r A-part
            float hA[4] = {}, hAe[4] = {};
            mma_acc<4>(&fH[8], bb, 256, hA, hAe);   // h A-part

            BSYNC(3, 256);    // W ready
            mma_acc<4>(&fR[0], bb, 0, cR, cRe);     // r W-part
            {
                float r00 = sigm_f(cR[0] + cRe[0] + br1);
                float r10 = sigm_f(cR[1] + cRe[1] + br1);
                float r01 = sigm_f(cR[2] + cRe[2] + br2);
                float r11 = sigm_f(cR[3] + cRe[3] + br2);
                S->st[n0 * SSTR + 192 + j1] =
                    __float2half(r00 * S->Ifp[n0 * GP + j1]);
                S->st[n1 * SSTR + 192 + j1] =
                    __float2half(r10 * S->Ifp[n1 * GP + j1]);
                S->st[n0 * SSTR + 192 + j2] =
                    __float2half(r01 * S->Ifp[n0 * GP + j2]);
                S->st[n1 * SSTR + 192 + j2] =
                    __float2half(r11 * S->Ifp[n1 * GP + j2]);
            }
            BSYNC(5, 128);    // RI visible

            mma_acc<4>(&fH[0], bb, 0, hA, hAe);     // h W-part
            float gA[4] = {}, gAe[4] = {};
            mma_acc<4>(&fAg[0], bb, 0, gA, gAe);    // Ag W-part (shadow)
            mma_acc<4>(&fH[4], bb, 384, hA, hAe);   // h RI-part
            BSYNC(4, 256);    // z ready
            {   // I epilogue
                float h00 = tanh_f(hA[0] + hAe[0] + bh1);
                float h10 = tanh_f(hA[1] + hAe[1] + bh1);
                float h01 = tanh_f(hA[2] + hAe[2] + bh2);
                float h11 = tanh_f(hA[3] + hAe[3] + bh2);
                float z00 = S->ztmp[n0 * GP + j1], z10 = S->ztmp[n1 * GP + j1];
                float z01 = S->ztmp[n0 * GP + j2], z11 = S->ztmp[n1 * GP + j2];
                float i00 = S->Ifp[n0 * GP + j1], i10 = S->Ifp[n1 * GP + j1];
                float i01 = S->Ifp[n0 * GP + j2], i11 = S->Ifp[n1 * GP + j2];
                float I00 = i00 + z00 * (h00 - i00);
                float I10 = i10 + z10 * (h10 - i10);
                float I01 = i01 + z01 * (h01 - i01);
                float I11 = i11 + z11 * (h11 - i11);
                S->Ifp[n0 * GP + j1] = I00; S->Ifp[n1 * GP + j1] = I10;
                S->Ifp[n0 * GP + j2] = I01; S->Ifp[n1 * GP + j2] = I11;
                S->st[n0 * SSTR + 64 + j1] = __float2half(I00);
                S->st[n1 * SSTR + 64 + j1] = __float2half(I10);
                S->st[n0 * SSTR + 64 + j2] = __float2half(I01);
                S->st[n1 * SSTR + 64 + j2] = __float2half(I11);
            }
            BARRIVE(6, 256);  // -> half0: I ready
            BSYNC(7, 128);    // I stores visible within half1

            mma_acc<4>(&fAg[4], bb, 128, gA, gAe);  // Ag I-part
            S->gtmp[n0 * GP + j1] = sigm_f(gA[0] + gAe[0] + ba1);
            S->gtmp[n1 * GP + j1] = sigm_f(gA[1] + gAe[1] + ba1);
            S->gtmp[n0 * GP + j2] = sigm_f(gA[2] + gAe[2] + ba2);
            S->gtmp[n1 * GP + j2] = sigm_f(gA[3] + gAe[3] + ba2);
            BARRIVE(8, 256);  // -> half0: Ag ready

            // ---- shadow for t+1: Wg [I], r [I] ----
#pragma unroll
            for (int i = 0; i < 4; i++) { cG[i] = 0.f; cGe[i] = 0.f;
                                          cR[i] = 0.f; cRe[i] = 0.f; }
            mma_acc<4>(&fG[0], bb, 128, cG, cGe);   // Wg I-part (I1)
            mma_acc<4>(&fR[4], bb, 128, cR, cRe);   // r I-part (I1)

            BSYNC(9, 256);    // A ready for next step top
        }
    }
}

extern "C" void kernel_launch(void* const* d_in, const int* in_sizes, int n_in,
                              void* d_out, int out_size) {
    (void)in_sizes; (void)n_in; (void)out_size;
    const size_t shmem = sizeof(Smem);
    cudaFuncSetAttribute(anima_kernel,
                         cudaFuncAttributeMaxDynamicSharedMemorySize,
                         (int)shmem);
    anima_kernel<<<NCTA, NTHREADS, shmem>>>(
        (const float*)d_in[0],
        (const float*)d_in[1], (const float*)d_in[2],
        (const float*)d_in[3], (const float*)d_in[4], (const float*)d_in[5],
        (const float*)d_in[6], (const float*)d_in[7],
        (const float*)d_in[8], (const float*)d_in[9],
        (const float*)d_in[10], (const float*)d_in[11],
        (const float*)d_in[12], (const float*)d_in[13],
        (const float*)d_in[14], (const float*)d_in[15], (const float*)d_in[16],
        (const float*)d_in[17], (const float*)d_in[18],
        (const float*)d_in[19], (const float*)d_in[20],
        (float*)d_out);
}

// round 16
// speedup vs baseline: 7.2130x; 1.1996x over previous
#include <cuda_runtime.h>
#include <cuda_fp16.h>
#include <cstdint>

#define TT 512
#define SDIM 8
#define ODIM 4
#define NTHREADS 256
#define NCTA 128

#define KP3 200   // padded row stride (halves) for 192-k weight blocks
#define KP2 136   // padded row stride for 128-k blocks
#define SSTR 264  // fp16 state row stride (halves): [W:0|I:64|A:128|RI:192]
#define GP  68    // fp32 temp row stride (floats)

struct __align__(16) Smem {
    __half win[64 * KP3];   // [j][ W|I|A ]   (W_from_*)
    __half wz [64 * KP3];   // [j][ Wn|I|A ]  (I_z)
    __half wr [64 * KP3];   // [j][ Wn|I|A ]  (I_r)
    __half wh [64 * KP3];   // [j][ Wn|rI|A ] (I_h)
    __half wa [64 * KP3];   // [j][ Wn|In|A ] (A_from_*)
    __half wg [64 * KP2];   // [j][ I|A ]     (W_gate)
    __half wag[64 * KP2];   // [j][ Wn|In ]   (A_gate)
    __half st [8 * SSTR];   // fp16 states per row: [W@0B | I@128B | A@256B | RI@384B]
    float gtmp[8 * GP];     // Wg sigm early-step; Ag sigm late-step
    float ztmp[8 * GP];     // z
    float Ifp [8 * GP];     // fp32 master of I
    float xs[8][SDIM];
};

extern __shared__ char smem_raw[];

// fast activations: MUFU.TANH based (abs err ~1e-4, subdominant to fp16 states)
__device__ __forceinline__ float tanh_f(float x) {
    float y;
    asm("tanh.approx.f32 %0, %1;" : "=f"(y) : "f"(x));
    return y;
}
__device__ __forceinline__ float sigm_f(float x) {
    float y;
    asm("tanh.approx.f32 %0, %1;" : "=f"(y) : "f"(0.5f * x));
    return fmaf(0.5f, y, 0.5f);
}
__device__ __forceinline__ uint32_t s2u(const void* p) {
    uint32_t a;
    asm("{ .reg .u64 t; cvta.to.shared.u64 t, %1; cvt.u32.u64 %0, t; }"
        : "=r"(a) : "l"(p));
    return a;
}
__device__ __forceinline__ void ldsm4(uint32_t addr, uint32_t& r0, uint32_t& r1,
                                      uint32_t& r2, uint32_t& r3) {
    asm volatile("ldmatrix.sync.aligned.m8n8.x4.shared.b16 {%0,%1,%2,%3}, [%4];"
                 : "=r"(r0), "=r"(r1), "=r"(r2), "=r"(r3) : "r"(addr));
}
__device__ __forceinline__ uint32_t lds32(uint32_t addr) {
    uint32_t v;
    asm volatile("ld.shared.b32 %0, [%1];" : "=r"(v) : "r"(addr));
    return v;
}
__device__ __forceinline__ void mma16816(float& d0, float& d1, float& d2, float& d3,
                                         uint32_t a0, uint32_t a1, uint32_t a2,
                                         uint32_t a3, uint32_t b0, uint32_t b1) {
    asm volatile(
        "mma.sync.aligned.m16n8k16.row.col.f32.f16.f16.f32 "
        "{%0,%1,%2,%3}, {%4,%5,%6,%7}, {%8,%9}, {%0,%1,%2,%3};"
        : "+f"(d0), "+f"(d1), "+f"(d2), "+f"(d3)
        : "r"(a0), "r"(a1), "r"(a2), "r"(a3), "r"(b0), "r"(b1));
}

#define BSYNC(id, n)   asm volatile("bar.sync %0, %1;"   :: "r"(id), "r"(n) : "memory")
#define BARRIVE(id, n) asm volatile("bar.arrive %0, %1;" :: "r"(id), "r"(n) : "memory")

// accumulate N k-tiles into (d,e): ALL B loads issued first (one LDS-latency
// exposure), then the mma chain (2 accumulator sets).
template <int N>
__device__ __forceinline__ void mma_acc(const uint32_t (*f)[4], uint32_t bb,
                                        int bstart, float (&d)[4], float (&e)[4]) {
    uint32_t b0[N], b1[N];
#pragma unroll
    for (int i = 0; i < N; i++) {
        b0[i] = lds32(bb + bstart + i * 32);
        b1[i] = lds32(bb + bstart + i * 32 + 16);
    }
#pragma unroll
    for (int i = 0; i < N; i++) {
        float* a = (i & 1) ? e : d;
        mma16816(a[0], a[1], a[2], a[3],
                 f[i][0], f[i][1], f[i][2], f[i][3], b0[i], b1[i]);
    }
}

__device__ __forceinline__ void stage_mat(__half* dst, int Kp, int koff,
                                          const float* __restrict__ src, int K) {
#pragma unroll 1
    for (int i = threadIdx.x; i < K * 64; i += NTHREADS) {
        int k = i >> 6, j = i & 63;
        dst[j * Kp + koff + k] = __float2half(src[i]);
    }
}

// Barriers (counts: 256 unless noted):
//  b1: Wg ready     (h1 arrive, h0 sync)
//  b3: W_new ready  (h0 arrive, h1 sync)
//  b4: z ready      (h0 arrive, h1 sync)
//  b6: I_new ready  (h1 arrive, h0 sync)
//  b8: Ag ready     (h1 arrive, h0 sync)
//  b9: A_new ready  (h0 arrive, h1 sync)
//  b2: half0 internal (128, twice per step)
//  b5, b7: half1 internal (128)

__global__ void __launch_bounds__(NTHREADS, 1)
anima_kernel(const float* __restrict__ x,
             const float* __restrict__ we_w, const float* __restrict__ we_b,
             const float* __restrict__ WfW, const float* __restrict__ WfI,
             const float* __restrict__ WfA,
             const float* __restrict__ Wg_w, const float* __restrict__ Wg_b,
             const float* __restrict__ Iz_w, const float* __restrict__ Iz_b,
             const float* __restrict__ Ir_w, const float* __restrict__ Ir_b,
             const float* __restrict__ Ih_w, const float* __restrict__ Ih_b,
             const float* __restrict__ AfW, const float* __restrict__ AfI,
             const float* __restrict__ AfA,
             const float* __restrict__ Ag_w, const float* __restrict__ Ag_b,
             const float* __restrict__ phi_w, const float* __restrict__ phi_b,
             float* __restrict__ out) {
    Smem* S = reinterpret_cast<Smem*>(smem_raw);
    const int tid = threadIdx.x;

    // ---- one-time staging (transposed, k-concatenated)
    stage_mat(S->win, KP3, 0, WfW, 64);
    stage_mat(S->win, KP3, 64, WfI, 64);
    stage_mat(S->win, KP3, 128, WfA, 64);
    stage_mat(S->wz, KP3, 0, Iz_w, 192);
    stage_mat(S->wr, KP3, 0, Ir_w, 192);
    stage_mat(S->wh, KP3, 0, Ih_w, 192);
    stage_mat(S->wa, KP3, 0, AfW, 64);
    stage_mat(S->wa, KP3, 64, AfI, 64);
    stage_mat(S->wa, KP3, 128, AfA, 64);
    stage_mat(S->wg, KP2, 0, Wg_w, 128);
    stage_mat(S->wag, KP2, 0, Ag_w, 128);

#pragma unroll 1
    for (int i = tid; i < 8 * SSTR / 2; i += NTHREADS)
        reinterpret_cast<uint32_t*>(S->st)[i] = 0u;
#pragma unroll 1
    for (int i = tid; i < 8 * GP; i += NTHREADS) S->Ifp[i] = 0.f;

    // ---- common mapping
    const int lane = tid & 31, w = tid >> 5;
    const int jt = w & 3;
    const int g = lane >> 2, t4 = lane & 3;
    const int rl = (lane & 7) | (((lane >> 3) & 1) << 3);
    const int c8 = (lane >> 4) * 8;
    const int j1 = jt * 16 + g, j2 = j1 + 8;
    const int n0 = 2 * t4, n1 = n0 + 1;
    const long base = (long)blockIdx.x * 8;
    const uint32_t arow3 = ((jt * 16 + rl) * KP3 + c8) * 2;
    const uint32_t arow2 = ((jt * 16 + rl) * KP2 + c8) * 2;
    const uint32_t bb = s2u(S->st) + g * (SSTR * 2) + t4 * 4;

    // stage x(0)
    const int xrow = tid >> 3, xc = tid & 7;
    const float* xptr = x + (base + xrow) * (TT * SDIM) + xc;
    if (tid < 64) S->xs[xrow][xc] = xptr[0];
    __syncthreads();

    if (w < 4) {
        // ============ half0: W_in, z, A_in, W/A epilogues, P5, x ============
        uint32_t fW[12][4], fZ[12][4], fA[12][4];
        {
            const uint32_t aW_ = s2u(S->win) + arow3;
            const uint32_t aZ_ = s2u(S->wz) + arow3;
            const uint32_t aA_ = s2u(S->wa) + arow3;
#pragma unroll
            for (int kt = 0; kt < 12; kt++)
                ldsm4(aW_ + kt * 32, fW[kt][0], fW[kt][1], fW[kt][2], fW[kt][3]);
#pragma unroll
            for (int kt = 0; kt < 12; kt++)
                ldsm4(aZ_ + kt * 32, fZ[kt][0], fZ[kt][1], fZ[kt][2], fZ[kt][3]);
#pragma unroll
            for (int kt = 0; kt < 12; kt++)
                ldsm4(aA_ + kt * 32, fA[kt][0], fA[kt][1], fA[kt][2], fA[kt][3]);
        }
        float we1[8], we2[8];
#pragma unroll
        for (int s = 0; s < 8; s++) {
            we1[s] = we_w[s * 64 + j1];
            we2[s] = we_w[s * 64 + j2];
        }
        const float be1 = we_b[j1], be2 = we_b[j2];
        const float bz1 = Iz_b[j1], bz2 = Iz_b[j2];
        const int o5 = lane & 3, sg = (lane >> 2) & 3, rsel = lane >> 4;
        const int prow = w * 2 + rsel;
        float ph[16];
#pragma unroll
        for (int kk = 0; kk < 16; kk++) ph[kk] = phi_w[(sg * 16 + kk) * 4 + o5];
        const float bphi = phi_b[o5];
        float xv = (tid < 64) ? xptr[SDIM] : 0.f;

        // carried partials (zero at t=0: states are zero) + enc(0)
        float cW[4] = {}, cWe[4] = {}, cZ[4] = {}, cZe[4] = {};
        float enc[4];
        {
            const float* x0 = S->xs[n0];
            const float* x1 = S->xs[n1];
            float e00 = be1, e10 = be1, e01 = be2, e11 = be2;
#pragma unroll
            for (int s = 0; s < 8; s++) {
                e00 = fmaf(x0[s], we1[s], e00);
                e10 = fmaf(x1[s], we1[s], e10);
                e01 = fmaf(x0[s], we2[s], e01);
                e11 = fmaf(x1[s], we2[s], e11);
            }
            enc[0] = tanh_f(e00); enc[1] = tanh_f(e10);
            enc[2] = tanh_f(e01); enc[3] = tanh_f(e11);
        }

        for (int t_ = 0; t_ < TT; t_++) {
            // -- step top: A(t-1)-dependent parts only
            mma_acc<4>(&fW[8], bb, 256, cW, cWe);   // W_in A-part
            float aA[4] = {}, aAe[4] = {};
            mma_acc<4>(&fA[8], bb, 256, aA, aAe);   // A_in A-part
            mma_acc<4>(&fZ[8], bb, 256, cZ, cZe);   // z A-part

            BSYNC(1, 256);  // Wg ready
            {   // W epilogue (enc pre-tanh'd in shadow)
                float w00 = tanh_f(cW[0] + cWe[0] + enc[0]) * S->gtmp[n0 * GP + j1];
                float w10 = tanh_f(cW[1] + cWe[1] + enc[1]) * S->gtmp[n1 * GP + j1];
                float w01 = tanh_f(cW[2] + cWe[2] + enc[2]) * S->gtmp[n0 * GP + j2];
                float w11 = tanh_f(cW[3] + cWe[3] + enc[3]) * S->gtmp[n1 * GP + j2];
                S->st[n0 * SSTR + j1] = __float2half(w00);
                S->st[n1 * SSTR + j1] = __float2half(w10);
                S->st[n0 * SSTR + j2] = __float2half(w01);
                S->st[n1 * SSTR + j2] = __float2half(w11);
            }
            BARRIVE(3, 256);  // -> half1: W ready
            BSYNC(2, 128);    // half0 internal: W stores visible

            // -- z W-part + store
            mma_acc<4>(&fZ[0], bb, 0, cZ, cZe);
            S->ztmp[n0 * GP + j1] = sigm_f(cZ[0] + cZe[0] + bz1);
            S->ztmp[n1 * GP + j1] = sigm_f(cZ[1] + cZe[1] + bz1);
            S->ztmp[n0 * GP + j2] = sigm_f(cZ[2] + cZe[2] + bz2);
            S->ztmp[n1 * GP + j2] = sigm_f(cZ[3] + cZe[3] + bz2);
            BARRIVE(4, 256);  // -> half1: z ready

            // -- A_in W-part (shadow w.r.t. I)
            mma_acc<4>(&fA[0], bb, 0, aA, aAe);
            BSYNC(6, 256);    // I_new ready
            mma_acc<4>(&fA[4], bb, 128, aA, aAe);   // A_in I-part
            BSYNC(8, 256);    // Ag ready
            {   // A epilogue
                float a00 = tanh_f(aA[0] + aAe[0]) * S->gtmp[n0 * GP + j1];
                float a10 = tanh_f(aA[1] + aAe[1]) * S->gtmp[n1 * GP + j1];
                float a01 = tanh_f(aA[2] + aAe[2]) * S->gtmp[n0 * GP + j2];
                float a11 = tanh_f(aA[3] + aAe[3]) * S->gtmp[n1 * GP + j2];
                S->st[n0 * SSTR + 128 + j1] = __float2half(a00);
                S->st[n1 * SSTR + 128 + j1] = __float2half(a10);
                S->st[n0 * SSTR + 128 + j2] = __float2half(a01);
                S->st[n1 * SSTR + 128 + j2] = __float2half(a11);
            }
            if (tid < 64) {
                S->xs[xrow][xc] = xv;  // x(t+1)
                if (t_ + 2 < TT) xv = xptr[(t_ + 2) * SDIM];
            }
            BARRIVE(9, 256);  // -> half1: A ready
            BSYNC(2, 128);    // half0 internal: A stores + xs visible

            // ---- shadow for t+1: W_in [W|I], z [I], enc, P5 ----
#pragma unroll
            for (int i = 0; i < 4; i++) { cW[i] = 0.f; cWe[i] = 0.f;
                                          cZ[i] = 0.f; cZe[i] = 0.f; }
            mma_acc<4>(&fW[0], bb, 0, cW, cWe);     // W-part (W1)
            mma_acc<4>(&fW[4], bb, 128, cW, cWe);   // I-part (I1)
            mma_acc<4>(&fZ[4], bb, 128, cZ, cZe);   // z I-part (I1)
            {
                const float* x0 = S->xs[n0];
                const float* x1 = S->xs[n1];
                float e00 = be1, e10 = be1, e01 = be2, e11 = be2;
#pragma unroll
                for (int s = 0; s < 8; s++) {
                    e00 = fmaf(x0[s], we1[s], e00);
                    e10 = fmaf(x1[s], we1[s], e10);
                    e01 = fmaf(x0[s], we2[s], e01);
                    e11 = fmaf(x1[s], we2[s], e11);
                }
                enc[0] = tanh_f(e00); enc[1] = tanh_f(e10);
                enc[2] = tanh_f(e01); enc[3] = tanh_f(e11);
            }
            {   // P5: action(t) = A_new @ phi + b
                const __half* ap = S->st + prow * SSTR + 128 + sg * 16;
                uint4 v0 = *reinterpret_cast<const uint4*>(ap);
                uint4 v1 = *reinterpret_cast<const uint4*>(ap + 8);
                const __half2* h0 = reinterpret_cast<const __half2*>(&v0);
                const __half2* h1 = reinterpret_cast<const __half2*>(&v1);
                float p = 0.f;
#pragma unroll
                for (int q = 0; q < 4; q++) {
                    float2 f0 = __half22float2(h0[q]);
                    float2 f1 = __half22float2(h1[q]);
                    p = fmaf(f0.x, ph[2 * q], p);
                    p = fmaf(f0.y, ph[2 * q + 1], p);
                    p = fmaf(f1.x, ph[8 + 2 * q], p);
                    p = fmaf(f1.y, ph[9 + 2 * q], p);
                }
                p += __shfl_xor_sync(0xffffffffu, p, 4);
                p += __shfl_xor_sync(0xffffffffu, p, 8);
                if (sg == 0)
                    out[(base + prow) * (TT * ODIM) + t_ * ODIM + o5] = p + bphi;
            }
        }
    } else {
        // ============ half1: Wg, r->RI, h->I_new, Ag ============
        uint32_t fG[8][4], fR[12][4], fH[12][4], fAg[8][4];
        {
            const uint32_t aG_ = s2u(S->wg) + arow2;
            const uint32_t aR_ = s2u(S->wr) + arow3;
            const uint32_t aH_ = s2u(S->wh) + arow3;
            const uint32_t aAg_ = s2u(S->wag) + arow2;
#pragma unroll
            for (int kt = 0; kt < 8; kt++)
                ldsm4(aG_ + kt * 32, fG[kt][0], fG[kt][1], fG[kt][2], fG[kt][3]);
#pragma unroll
            for (int kt = 0; kt < 12; kt++)
                ldsm4(aR_ + kt * 32, fR[kt][0], fR[kt][1], fR[kt][2], fR[kt][3]);
#pragma unroll
            for (int kt = 0; kt < 12; kt++)
                ldsm4(aH_ + kt * 32, fH[kt][0], fH[kt][1], fH[kt][2], fH[kt][3]);
#pragma unroll
            for (int kt = 0; kt < 8; kt++)
                ldsm4(aAg_ + kt * 32, fAg[kt][0], fAg[kt][1], fAg[kt][2], fAg[kt][3]);
        }
        const float bg1 = Wg_b[j1], bg2 = Wg_b[j2];
        const float br1 = Ir_b[j1], br2 = Ir_b[j2];
        const float bh1 = Ih_b[j1], bh2 = Ih_b[j2];
        const float ba1 = Ag_b[j1], ba2 = Ag_b[j2];

        // carried partials (zero at t=0)
        float cG[4] = {}, cGe[4] = {}, cR[4] = {}, cRe[4] = {};

        for (int t_ = 0; t_ < TT; t_++) {
            // -- step top: Wg A-part, then store gate
            mma_acc<4>(&fG[4], bb, 256, cG, cGe);
            S->gtmp[n0 * GP + j1] = sigm_f(cG[0] + cGe[0] + bg1);
            S->gtmp[n1 * GP + j1] = sigm_f(cG[1] + cGe[1] + bg1);
            S->gtmp[n0 * GP + j2] = sigm_f(cG[2] + cGe[2] + bg2);
            S->gtmp[n1 * GP + j2] = sigm_f(cG[3] + cGe[3] + bg2);
            BARRIVE(1, 256);  // -> half0: Wg ready

            // -- A-dependent precomputes (off critical path)
            mma_acc<4>(&fR[8], bb, 256, cR, cRe);   // r A-part
            float hA[4] = {}, hAe[4] = {};
            mma_acc<4>(&fH[8], bb, 256, hA, hAe);   // h A-part

            BSYNC(3, 256);    // W ready
            mma_acc<4>(&fR[0], bb, 0, cR, cRe);     // r W-part
            {
                float r00 = sigm_f(cR[0] + cRe[0] + br1);
                float r10 = sigm_f(cR[1] + cRe[1] + br1);
                float r01 = sigm_f(cR[2] + cRe[2] + br2);
                float r11 = sigm_f(cR[3] + cRe[3] + br2);
                S->st[n0 * SSTR + 192 + j1] =
                    __float2half(r00 * S->Ifp[n0 * GP + j1]);
                S->st[n1 * SSTR + 192 + j1] =
                    __float2half(r10 * S->Ifp[n1 * GP + j1]);
                S->st[n0 * SSTR + 192 + j2] =
                    __float2half(r01 * S->Ifp[n0 * GP + j2]);
                S->st[n1 * SSTR + 192 + j2] =
                    __float2half(r11 * S->Ifp[n1 * GP + j2]);
            }
            BSYNC(5, 128);    // RI visible

            mma_acc<4>(&fH[0], bb, 0, hA, hAe);     // h W-part
            float gA[4] = {}, gAe[4] = {};
            mma_acc<4>(&fAg[0], bb, 0, gA, gAe);    // Ag W-part (shadow)
            mma_acc<4>(&fH[4], bb, 384, hA, hAe);   // h RI-part
            BSYNC(4, 256);    // z ready
            {   // I epilogue
                float h00 = tanh_f(hA[0] + hAe[0] + bh1);
                float h10 = tanh_f(hA[1] + hAe[1] + bh1);
                float h01 = tanh_f(hA[2] + hAe[2] + bh2);
                float h11 = tanh_f(hA[3] + hAe[3] + bh2);
                float z00 = S->ztmp[n0 * GP + j1], z10 = S->ztmp[n1 * GP + j1];
                float z01 = S->ztmp[n0 * GP + j2], z11 = S->ztmp[n1 * GP + j2];
                float i00 = S->Ifp[n0 * GP + j1], i10 = S->Ifp[n1 * GP + j1];
                float i01 = S->Ifp[n0 * GP + j2], i11 = S->Ifp[n1 * GP + j2];
                float I00 = i00 + z00 * (h00 - i00);
                float I10 = i10 + z10 * (h10 - i10);
                float I01 = i01 + z01 * (h01 - i01);
                float I11 = i11 + z11 * (h11 - i11);
                S->Ifp[n0 * GP + j1] = I00; S->Ifp[n1 * GP + j1] = I10;
                S->Ifp[n0 * GP + j2] = I01; S->Ifp[n1 * GP + j2] = I11;
                S->st[n0 * SSTR + 64 + j1] = __float2half(I00);
                S->st[n1 * SSTR + 64 + j1] = __float2half(I10);
                S->st[n0 * SSTR + 64 + j2] = __float2half(I01);
                S->st[n1 * SSTR + 64 + j2] = __float2half(I11);
            }
            BARRIVE(6, 256);  // -> half0: I ready
            BSYNC(7, 128);    // I stores visible within half1

            mma_acc<4>(&fAg[4], bb, 128, gA, gAe);  // Ag I-part
            S->gtmp[n0 * GP + j1] = sigm_f(gA[0] + gAe[0] + ba1);
            S->gtmp[n1 * GP + j1] = sigm_f(gA[1] + gAe[1] + ba1);
            S->gtmp[n0 * GP + j2] = sigm_f(gA[2] + gAe[2] + ba2);
            S->gtmp[n1 * GP + j2] = sigm_f(gA[3] + gAe[3] + ba2);
            BARRIVE(8, 256);  // -> half0: Ag ready

            // ---- shadow for t+1: Wg [I], r [I] ----
#pragma unroll
            for (int i = 0; i < 4; i++) { cG[i] = 0.f; cGe[i] = 0.f;
                                          cR[i] = 0.f; cRe[i] = 0.f; }
            mma_acc<4>(&fG[0], bb, 128, cG, cGe);   // Wg I-part (I1)
            mma_acc<4>(&fR[4], bb, 128, cR, cRe);   // r I-part (I1)

            BSYNC(9, 256);    // A ready for next step top
        }
    }
}

extern "C" void kernel_launch(void* const* d_in, const int* in_sizes, int n_in,
                              void* d_out, int out_size) {
    (void)in_sizes; (void)n_in; (void)out_size;
    const size_t shmem = sizeof(Smem);
    cudaFuncSetAttribute(anima_kernel,
                         cudaFuncAttributeMaxDynamicSharedMemorySize,
                         (int)shmem);
    anima_kernel<<<NCTA, NTHREADS, shmem>>>(
        (const float*)d_in[0],
        (const float*)d_in[1], (const float*)d_in[2],
        (const float*)d_in[3], (const float*)d_in[4], (const float*)d_in[5],
        (const float*)d_in[6], (const float*)d_in[7],
        (const float*)d_in[8], (const float*)d_in[9],
        (const float*)d_in[10], (const float*)d_in[11],
        (const float*)d_in[12], (const float*)d_in[13],
        (const float*)d_in[14], (const float*)d_in[15], (const float*)d_in[16],
        (const float*)d_in[17], (const float*)d_in[18],
        (const float*)d_in[19], (const float*)d_in[20],
        (float*)d_out);
}